// round 1
// baseline (speedup 1.0000x reference)
#include <cuda_runtime.h>

// ---------------- problem-size constants (fixed by the reference) ----------
#define NNODES   50000
#define NEDGES   800000
#define ETOT     (NNODES + NEDGES)      // 850000 (edges + self loops)
#define SCAN_BS  512

// ---------------- device scratch (no allocations allowed) ------------------
__device__ float g_l0[(size_t)NNODES * 256];   // [x@W0^T | x@linW0^T]
__device__ float g_h [(size_t)NNODES * 128];   // layer-0 output (post ELU)
__device__ float g_l1[(size_t)NNODES * 64];    // [h@W1^T | h@linW1^T]
__device__ float g_as0[NNODES * 4];
__device__ float g_ad0[NNODES * 4];
__device__ float g_as1[NNODES];
__device__ float g_ad1[NNODES];
__device__ int   g_deg[NNODES + 64];
__device__ int   g_rowtmp[NNODES + 64];
__device__ int   g_rowptr[NNODES + 64];
__device__ int   g_cursor[NNODES + 64];
__device__ int   g_csr_src[ETOT + 64];
__device__ int   g_bsum[SCAN_BS];
__device__ int   g_boff[SCAN_BS];
__device__ float g_B0[256 * 128];
__device__ float g_B1[64 * 128];

// ---------------- pack weight matrices into concatenated B -----------------
__global__ void k_pack(const float* __restrict__ W0, const float* __restrict__ lW0,
                       const float* __restrict__ W1, const float* __restrict__ lW1) {
    int i = blockIdx.x * blockDim.x + threadIdx.x;
    if (i < 128 * 128) { g_B0[i] = W0[i]; g_B0[128 * 128 + i] = lW0[i]; }
    if (i < 32 * 128)  { g_B1[i] = W1[i]; g_B1[32 * 128 + i]  = lW1[i]; }
}

// ---------------- CSR build -------------------------------------------------
__global__ void k_zero_deg(int n) {
    int i = blockIdx.x * blockDim.x + threadIdx.x;
    if (i < n) g_deg[i] = 0;
}

__global__ void k_hist(const int* __restrict__ ei, int e, int etot) {
    int k = blockIdx.x * blockDim.x + threadIdx.x;
    if (k >= etot) return;
    int dst = (k < e) ? ei[e + k] : (k - e);
    atomicAdd(&g_deg[dst], 1);
}

__global__ void k_scan1(int n) {
    __shared__ int sh[SCAN_BS];
    int t = threadIdx.x;
    int i = blockIdx.x * SCAN_BS + t;
    int v = (i < n) ? g_deg[i] : 0;
    sh[t] = v;
    __syncthreads();
    for (int o = 1; o < SCAN_BS; o <<= 1) {
        int x = (t >= o) ? sh[t - o] : 0;
        __syncthreads();
        sh[t] += x;
        __syncthreads();
    }
    if (i < n) g_rowtmp[i] = sh[t];
    if (t == SCAN_BS - 1) g_bsum[blockIdx.x] = sh[t];
}

__global__ void k_scan2(int nb) {
    __shared__ int sh[SCAN_BS];
    int t = threadIdx.x;
    int v = (t < nb) ? g_bsum[t] : 0;
    sh[t] = v;
    __syncthreads();
    for (int o = 1; o < SCAN_BS; o <<= 1) {
        int x = (t >= o) ? sh[t - o] : 0;
        __syncthreads();
        sh[t] += x;
        __syncthreads();
    }
    if (t < nb) g_boff[t] = sh[t] - v;   // exclusive offsets
}

__global__ void k_scan3(int n) {
    int i = blockIdx.x * blockDim.x + threadIdx.x;
    if (i >= n) return;
    int incl = g_rowtmp[i] + g_boff[i >> 9];   // 512 == 1<<9
    g_rowptr[i + 1] = incl;
    g_cursor[i] = incl - g_deg[i];
    if (i == 0) g_rowptr[0] = 0;
}

__global__ void k_scatter(const int* __restrict__ ei, int e, int etot) {
    int k = blockIdx.x * blockDim.x + threadIdx.x;
    if (k >= etot) return;
    int src, dst;
    if (k < e) { src = ei[k]; dst = ei[e + k]; }
    else       { src = dst = k - e; }
    int pos = atomicAdd(&g_cursor[dst], 1);
    g_csr_src[pos] = src;
}

// ---------------- GEMM: C[M,NN] = A[M,128] * B[NN,128]^T -------------------
// Entire B tile lives in shared (NN<=256 -> 132-padded rows, conflict-free
// LDS.128). 512 threads, each computes 4 rows x JC cols, block covers 64 rows.
template <int JC>
__global__ void __launch_bounds__(512) k_gemm(const float* __restrict__ Aext, int M) {
    constexpr int NN = 32 * JC;
    extern __shared__ float sh[];
    float* Bs = sh;                 // [NN][132]
    float* Xs = sh + NN * 132;      // [64][132]

    const float* A  = (JC == 8) ? Aext : (const float*)g_h;
    const float* Bg = (JC == 8) ? (const float*)g_B0 : (const float*)g_B1;
    float*       C  = (JC == 8) ? g_l0 : g_l1;

    int t = threadIdx.x;
    for (int idx = t; idx < NN * 32; idx += 512) {
        int row = idx >> 5, k4 = idx & 31;
        float4 v = *(const float4*)(Bg + row * 128 + k4 * 4);
        *(float4*)(Bs + row * 132 + k4 * 4) = v;
    }
    int base = blockIdx.x * 64;
    for (int idx = t; idx < 64 * 32; idx += 512) {
        int row = idx >> 5, k4 = idx & 31;
        int gr = base + row;
        float4 v = make_float4(0.f, 0.f, 0.f, 0.f);
        if (gr < M) v = *(const float4*)(A + (size_t)gr * 128 + k4 * 4);
        *(float4*)(Xs + row * 132 + k4 * 4) = v;
    }
    __syncthreads();

    int cg = t & 31, rg = t >> 5;   // rg 0..15 -> rows, cg 0..31 -> col lanes
    float acc[4][JC];
#pragma unroll
    for (int i = 0; i < 4; i++)
#pragma unroll
        for (int j = 0; j < JC; j++) acc[i][j] = 0.f;

#pragma unroll 4
    for (int kq = 0; kq < 32; kq++) {
        float4 a[4];
#pragma unroll
        for (int i = 0; i < 4; i++)
            a[i] = *(const float4*)(Xs + (rg * 4 + i) * 132 + kq * 4);
        float4 b[JC];
#pragma unroll
        for (int j = 0; j < JC; j++)
            b[j] = *(const float4*)(Bs + (j * 32 + cg) * 132 + kq * 4);
#pragma unroll
        for (int i = 0; i < 4; i++)
#pragma unroll
            for (int j = 0; j < JC; j++) {
                acc[i][j] = fmaf(a[i].x, b[j].x, acc[i][j]);
                acc[i][j] = fmaf(a[i].y, b[j].y, acc[i][j]);
                acc[i][j] = fmaf(a[i].z, b[j].z, acc[i][j]);
                acc[i][j] = fmaf(a[i].w, b[j].w, acc[i][j]);
            }
    }

#pragma unroll
    for (int i = 0; i < 4; i++) {
        int gr = base + rg * 4 + i;
        if (gr < M) {
#pragma unroll
            for (int j = 0; j < JC; j++)
                C[(size_t)gr * NN + j * 32 + cg] = acc[i][j];
        }
    }
}

// ---------------- attention logits ------------------------------------------
__global__ void k_att0(const float* __restrict__ as, const float* __restrict__ adw, int n) {
    int gw = (blockIdx.x * blockDim.x + threadIdx.x) >> 5;
    int lane = threadIdx.x & 31;
    if (gw >= n) return;
    float4 v  = *(const float4*)(g_l0 + (size_t)gw * 256 + lane * 4);
    float4 s4 = *(const float4*)(as + lane * 4);
    float4 d4 = *(const float4*)(adw + lane * 4);
    float s = v.x * s4.x + v.y * s4.y + v.z * s4.z + v.w * s4.w;
    float d = v.x * d4.x + v.y * d4.y + v.z * d4.z + v.w * d4.w;
#pragma unroll
    for (int o = 4; o; o >>= 1) {
        s += __shfl_down_sync(0xffffffffu, s, o, 8);
        d += __shfl_down_sync(0xffffffffu, d, o, 8);
    }
    if ((lane & 7) == 0) {
        int h = lane >> 3;
        g_as0[gw * 4 + h] = s;
        g_ad0[gw * 4 + h] = d;
    }
}

__global__ void k_att1(const float* __restrict__ as, const float* __restrict__ adw, int n) {
    int gw = (blockIdx.x * blockDim.x + threadIdx.x) >> 5;
    int lane = threadIdx.x & 31;
    if (gw >= n) return;
    float v = g_l1[(size_t)gw * 64 + lane];
    float s = v * as[lane];
    float d = v * adw[lane];
#pragma unroll
    for (int o = 16; o; o >>= 1) {
        s += __shfl_xor_sync(0xffffffffu, s, o);
        d += __shfl_xor_sync(0xffffffffu, d, o);
    }
    if (lane == 0) { g_as1[gw] = s; g_ad1[gw] = d; }
}

// ---------------- layer-0 aggregation: warp per dst node --------------------
__global__ void k_agg0(const float* __restrict__ bias0, const float* __restrict__ linb0, int n) {
    int gw = (blockIdx.x * blockDim.x + threadIdx.x) >> 5;
    int lane = threadIdx.x & 31;
    if (gw >= n) return;
    int beg = g_rowptr[gw], end = g_rowptr[gw + 1];
    float4 ad = *(const float4*)(g_ad0 + gw * 4);

    float mx0 = -1e30f, mx1 = -1e30f, mx2 = -1e30f, mx3 = -1e30f;
    for (int i = beg + lane; i < end; i += 32) {
        int s = g_csr_src[i];
        float4 av = *(const float4*)(g_as0 + s * 4);
        float e0 = av.x + ad.x; e0 = e0 > 0.f ? e0 : 0.2f * e0;
        float e1 = av.y + ad.y; e1 = e1 > 0.f ? e1 : 0.2f * e1;
        float e2 = av.z + ad.z; e2 = e2 > 0.f ? e2 : 0.2f * e2;
        float e3 = av.w + ad.w; e3 = e3 > 0.f ? e3 : 0.2f * e3;
        mx0 = fmaxf(mx0, e0); mx1 = fmaxf(mx1, e1);
        mx2 = fmaxf(mx2, e2); mx3 = fmaxf(mx3, e3);
    }
#pragma unroll
    for (int o = 16; o; o >>= 1) {
        mx0 = fmaxf(mx0, __shfl_xor_sync(0xffffffffu, mx0, o));
        mx1 = fmaxf(mx1, __shfl_xor_sync(0xffffffffu, mx1, o));
        mx2 = fmaxf(mx2, __shfl_xor_sync(0xffffffffu, mx2, o));
        mx3 = fmaxf(mx3, __shfl_xor_sync(0xffffffffu, mx3, o));
    }

    float dn0 = 0.f, dn1 = 0.f, dn2 = 0.f, dn3 = 0.f;
    for (int i = beg + lane; i < end; i += 32) {
        int s = g_csr_src[i];
        float4 av = *(const float4*)(g_as0 + s * 4);
        float e0 = av.x + ad.x; e0 = e0 > 0.f ? e0 : 0.2f * e0; dn0 += __expf(e0 - mx0);
        float e1 = av.y + ad.y; e1 = e1 > 0.f ? e1 : 0.2f * e1; dn1 += __expf(e1 - mx1);
        float e2 = av.z + ad.z; e2 = e2 > 0.f ? e2 : 0.2f * e2; dn2 += __expf(e2 - mx2);
        float e3 = av.w + ad.w; e3 = e3 > 0.f ? e3 : 0.2f * e3; dn3 += __expf(e3 - mx3);
    }
#pragma unroll
    for (int o = 16; o; o >>= 1) {
        dn0 += __shfl_xor_sync(0xffffffffu, dn0, o);
        dn1 += __shfl_xor_sync(0xffffffffu, dn1, o);
        dn2 += __shfl_xor_sync(0xffffffffu, dn2, o);
        dn3 += __shfl_xor_sync(0xffffffffu, dn3, o);
    }
    float inv0 = 1.f / (dn0 + 1e-16f);
    float inv1 = 1.f / (dn1 + 1e-16f);
    float inv2 = 1.f / (dn2 + 1e-16f);
    float inv3 = 1.f / (dn3 + 1e-16f);

    int   hsel  = lane & 3;
    float adsel = g_ad0[gw * 4 + hsel];
    float mxsel = (hsel == 0) ? mx0 : (hsel == 1) ? mx1 : (hsel == 2) ? mx2 : mx3;

    float acc0 = 0.f, acc1 = 0.f, acc2 = 0.f, acc3 = 0.f;
    for (int i = beg; i < end; i++) {
        int s = g_csr_src[i];
        float e = g_as0[s * 4 + hsel] + adsel;
        e = e > 0.f ? e : 0.2f * e;
        float we = __expf(e - mxsel);
        float w0 = __shfl_sync(0xffffffffu, we, 0);
        float w1 = __shfl_sync(0xffffffffu, we, 1);
        float w2 = __shfl_sync(0xffffffffu, we, 2);
        float w3 = __shfl_sync(0xffffffffu, we, 3);
        const float* row = g_l0 + (size_t)s * 256;
        acc0 = fmaf(w0, row[lane],      acc0);
        acc1 = fmaf(w1, row[32 + lane], acc1);
        acc2 = fmaf(w2, row[64 + lane], acc2);
        acc3 = fmaf(w3, row[96 + lane], acc3);
    }

    const float* skip = g_l0 + (size_t)gw * 256 + 128;
    float o0 = acc0 * inv0 + bias0[lane]      + linb0[lane]      + skip[lane];
    float o1 = acc1 * inv1 + bias0[32 + lane] + linb0[32 + lane] + skip[32 + lane];
    float o2 = acc2 * inv2 + bias0[64 + lane] + linb0[64 + lane] + skip[64 + lane];
    float o3 = acc3 * inv3 + bias0[96 + lane] + linb0[96 + lane] + skip[96 + lane];
    o0 = o0 > 0.f ? o0 : (__expf(o0) - 1.f);
    o1 = o1 > 0.f ? o1 : (__expf(o1) - 1.f);
    o2 = o2 > 0.f ? o2 : (__expf(o2) - 1.f);
    o3 = o3 > 0.f ? o3 : (__expf(o3) - 1.f);
    float* hr = g_h + (size_t)gw * 128;
    hr[lane] = o0; hr[32 + lane] = o1; hr[64 + lane] = o2; hr[96 + lane] = o3;
}

// ---------------- layer-1 aggregation: warp per dst node --------------------
__global__ void k_agg1(const float* __restrict__ bias1, const float* __restrict__ linb1,
                       float* __restrict__ out, int n) {
    int gw = (blockIdx.x * blockDim.x + threadIdx.x) >> 5;
    int lane = threadIdx.x & 31;
    if (gw >= n) return;
    int beg = g_rowptr[gw], end = g_rowptr[gw + 1];
    float ad = g_ad1[gw];

    float mx = -1e30f;
    for (int i = beg + lane; i < end; i += 32) {
        float e = g_as1[g_csr_src[i]] + ad;
        e = e > 0.f ? e : 0.2f * e;
        mx = fmaxf(mx, e);
    }
#pragma unroll
    for (int o = 16; o; o >>= 1) mx = fmaxf(mx, __shfl_xor_sync(0xffffffffu, mx, o));

    float dn = 0.f;
    for (int i = beg + lane; i < end; i += 32) {
        float e = g_as1[g_csr_src[i]] + ad;
        e = e > 0.f ? e : 0.2f * e;
        dn += __expf(e - mx);
    }
#pragma unroll
    for (int o = 16; o; o >>= 1) dn += __shfl_xor_sync(0xffffffffu, dn, o);
    float inv = 1.f / (dn + 1e-16f);

    float acc = 0.f;
    for (int i = beg; i < end; i++) {
        int s = g_csr_src[i];
        float e = g_as1[s] + ad;
        e = e > 0.f ? e : 0.2f * e;
        float we = __expf(e - mx);
        acc = fmaf(we, g_l1[(size_t)s * 64 + lane], acc);
    }
    out[(size_t)gw * 32 + lane] =
        acc * inv + bias1[lane] + linb1[lane] + g_l1[(size_t)gw * 64 + 32 + lane];
}

// ---------------- launcher ---------------------------------------------------
extern "C" void kernel_launch(void* const* d_in, const int* in_sizes, int n_in,
                              void* d_out, int out_size) {
    const float* x   = (const float*)d_in[0];
    const int*   ei  = (const int*)  d_in[1];
    const float* W0  = (const float*)d_in[2];
    const float* as0 = (const float*)d_in[3];
    const float* ad0 = (const float*)d_in[4];
    const float* b0  = (const float*)d_in[5];
    const float* lW0 = (const float*)d_in[6];
    const float* lb0 = (const float*)d_in[7];
    const float* W1  = (const float*)d_in[8];
    const float* as1 = (const float*)d_in[9];
    const float* ad1 = (const float*)d_in[10];
    const float* b1  = (const float*)d_in[11];
    const float* lW1 = (const float*)d_in[12];
    const float* lb1 = (const float*)d_in[13];
    float* out = (float*)d_out;

    int n = in_sizes[0] / 128;
    int e = in_sizes[1] / 2;
    int etot = n + e;
    int nb = (n + SCAN_BS - 1) / SCAN_BS;

    const int smem0 = (256 * 132 + 64 * 132) * (int)sizeof(float);  // 168960
    const int smem1 = (64 * 132 + 64 * 132)  * (int)sizeof(float);  // 67584
    cudaFuncSetAttribute(k_gemm<8>, cudaFuncAttributeMaxDynamicSharedMemorySize, smem0);
    cudaFuncSetAttribute(k_gemm<2>, cudaFuncAttributeMaxDynamicSharedMemorySize, smem1);

    // weights pack + CSR build
    k_pack<<<(128 * 128 + 255) / 256, 256>>>(W0, lW0, W1, lW1);
    k_zero_deg<<<(n + 255) / 256, 256>>>(n);
    k_hist<<<(etot + 255) / 256, 256>>>(ei, e, etot);
    k_scan1<<<nb, SCAN_BS>>>(n);
    k_scan2<<<1, SCAN_BS>>>(nb);
    k_scan3<<<(n + 255) / 256, 256>>>(n);
    k_scatter<<<(etot + 255) / 256, 256>>>(ei, e, etot);

    // layer 0
    k_gemm<8><<<(n + 63) / 64, 512, smem0>>>(x, n);
    k_att0<<<(n + 7) / 8, 256>>>(as0, ad0, n);
    k_agg0<<<(n + 7) / 8, 256>>>(b0, lb0, n);

    // layer 1
    k_gemm<2><<<(n + 63) / 64, 512, smem1>>>(x /*unused*/, n);
    k_att1<<<(n + 7) / 8, 256>>>(as1, ad1, n);
    k_agg1<<<(n + 7) / 8, 256>>>(b1, lb1, out, n);
}

// round 6
// speedup vs baseline: 1.0322x; 1.0322x over previous
#include <cuda_runtime.h>
#include <cuda_bf16.h>
#include <mma.h>
#include <cstdint>

using namespace nvcuda;

// ---------------- problem-size constants (fixed by the reference) ----------
#define NNODES   50000
#define NPAD     50048                  // padded to multiple of 128
#define NEDGES   800000
#define ETOT     (NNODES + NEDGES)      // 850000 (edges + self loops)
#define SCAN_BS  512

// ---------------- device scratch (no allocations allowed) ------------------
// NOTE: these are ONLY referenced from device code. Passing a __device__
// symbol as a host-side kernel argument passes the host shadow address,
// which GB300's ATS silently accepts -> zero output (root cause of R3-R5).
__device__ float g_l0[(size_t)NPAD * 256];   // [x@W0^T | x@linW0^T]
__device__ float g_l1[(size_t)NPAD * 64];    // [h@W1^T | h@linW1^T]
__device__ __nv_bfloat16 g_xh[(size_t)NPAD * 128];
__device__ __nv_bfloat16 g_xl[(size_t)NPAD * 128];
__device__ __nv_bfloat16 g_hh[(size_t)NPAD * 128];
__device__ __nv_bfloat16 g_hl[(size_t)NPAD * 128];
__device__ float g_as0[NNODES * 4];
__device__ float g_ad0[NNODES * 4];
__device__ float g_as1[NNODES];
__device__ float g_ad1[NNODES];
__device__ int   g_deg[NNODES + 64];
__device__ int   g_rowtmp[NNODES + 64];
__device__ int   g_rowptr[NNODES + 64];
__device__ int   g_cursor[NNODES + 64];
__device__ int   g_csr_src[ETOT + 64];
__device__ int   g_bsum[SCAN_BS];
__device__ int   g_boff[SCAN_BS];
__device__ __nv_bfloat16 g_B0h[256 * 128];
__device__ __nv_bfloat16 g_B0l[256 * 128];
__device__ __nv_bfloat16 g_B1h[64 * 128];
__device__ __nv_bfloat16 g_B1l[64 * 128];

// ---------------- weight prep: fp32 -> bf16 hi/lo ---------------------------
__global__ void k_prep(const float* __restrict__ W0, const float* __restrict__ lW0,
                       const float* __restrict__ W1, const float* __restrict__ lW1) {
    int i = blockIdx.x * blockDim.x + threadIdx.x;
    if (i < 128 * 128) {
        float v = W0[i];
        __nv_bfloat16 h = __float2bfloat16_rn(v);
        g_B0h[i] = h; g_B0l[i] = __float2bfloat16_rn(v - __bfloat162float(h));
        v = lW0[i];
        h = __float2bfloat16_rn(v);
        g_B0h[128 * 128 + i] = h; g_B0l[128 * 128 + i] = __float2bfloat16_rn(v - __bfloat162float(h));
    }
    if (i < 32 * 128) {
        float v = W1[i];
        __nv_bfloat16 h = __float2bfloat16_rn(v);
        g_B1h[i] = h; g_B1l[i] = __float2bfloat16_rn(v - __bfloat162float(h));
        v = lW1[i];
        h = __float2bfloat16_rn(v);
        g_B1h[32 * 128 + i] = h; g_B1l[32 * 128 + i] = __float2bfloat16_rn(v - __bfloat162float(h));
    }
}

// ---------------- x prep: fp32 -> bf16 hi/lo into g_xh/g_xl -----------------
__global__ void k_split(const float* __restrict__ src, int nquads) {
    int i = blockIdx.x * blockDim.x + threadIdx.x;
    if (i >= nquads) return;
    float4 v = ((const float4*)src)[i];
    __nv_bfloat16 hx = __float2bfloat16_rn(v.x), hy = __float2bfloat16_rn(v.y);
    __nv_bfloat16 hz = __float2bfloat16_rn(v.z), hw = __float2bfloat16_rn(v.w);
    int b = i * 4;
    g_xh[b]     = hx; g_xl[b]     = __float2bfloat16_rn(v.x - __bfloat162float(hx));
    g_xh[b + 1] = hy; g_xl[b + 1] = __float2bfloat16_rn(v.y - __bfloat162float(hy));
    g_xh[b + 2] = hz; g_xl[b + 2] = __float2bfloat16_rn(v.z - __bfloat162float(hz));
    g_xh[b + 3] = hw; g_xl[b + 3] = __float2bfloat16_rn(v.w - __bfloat162float(hw));
}

// ---------------- CSR build -------------------------------------------------
__global__ void k_zero_deg(int n) {
    int i = blockIdx.x * blockDim.x + threadIdx.x;
    if (i < n) g_deg[i] = 0;
}

__global__ void k_hist(const int* __restrict__ ei, int e, int etot) {
    int k = blockIdx.x * blockDim.x + threadIdx.x;
    if (k >= etot) return;
    int dst = (k < e) ? ei[e + k] : (k - e);
    atomicAdd(&g_deg[dst], 1);
}

__global__ void k_scan1(int n) {
    __shared__ int sh[SCAN_BS];
    int t = threadIdx.x;
    int i = blockIdx.x * SCAN_BS + t;
    int v = (i < n) ? g_deg[i] : 0;
    sh[t] = v;
    __syncthreads();
    for (int o = 1; o < SCAN_BS; o <<= 1) {
        int x = (t >= o) ? sh[t - o] : 0;
        __syncthreads();
        sh[t] += x;
        __syncthreads();
    }
    if (i < n) g_rowtmp[i] = sh[t];
    if (t == SCAN_BS - 1) g_bsum[blockIdx.x] = sh[t];
}

__global__ void k_scan2(int nb) {
    __shared__ int sh[SCAN_BS];
    int t = threadIdx.x;
    int v = (t < nb) ? g_bsum[t] : 0;
    sh[t] = v;
    __syncthreads();
    for (int o = 1; o < SCAN_BS; o <<= 1) {
        int x = (t >= o) ? sh[t - o] : 0;
        __syncthreads();
        sh[t] += x;
        __syncthreads();
    }
    if (t < nb) g_boff[t] = sh[t] - v;   // exclusive offsets
}

__global__ void k_scan3(int n) {
    int i = blockIdx.x * blockDim.x + threadIdx.x;
    if (i >= n) return;
    int incl = g_rowtmp[i] + g_boff[i >> 9];
    g_rowptr[i + 1] = incl;
    g_cursor[i] = incl - g_deg[i];
    if (i == 0) g_rowptr[0] = 0;
}

__global__ void k_scatter(const int* __restrict__ ei, int e, int etot) {
    int k = blockIdx.x * blockDim.x + threadIdx.x;
    if (k >= etot) return;
    int src, dst;
    if (k < e) { src = ei[k]; dst = ei[e + k]; }
    else       { src = dst = k - e; }
    int pos = atomicAdd(&g_cursor[dst], 1);
    g_csr_src[pos] = src;
}

// ---------------- WMMA GEMM: C[:, noff..] = A * B^T -------------------------
// fp32 via 3-product bf16 split (Ah*Bh + Al*Bh + Ah*Bl), fp32 accum.
// L=0: A=g_xh/g_xl, B=g_B0*, C=g_l0(CS=256). L=1: A=g_hh/g_hl, B=g_B1*, C=g_l1(CS=64).
// 8 warps: 4 along m x 2 along n. Warp tile = WM*16 rows x WN*16 cols.
// All operands straight from global (L1-resident). Globals referenced in-kernel.
template <int L, int WM, int WN, int CS>
__global__ void __launch_bounds__(256) k_wmma(int noff)
{
    const __nv_bfloat16* __restrict__ Ah = (L == 0) ? g_xh : g_hh;
    const __nv_bfloat16* __restrict__ Al = (L == 0) ? g_xl : g_hl;
    const __nv_bfloat16* __restrict__ Bh = (L == 0) ? g_B0h : g_B1h;
    const __nv_bfloat16* __restrict__ Bl = (L == 0) ? g_B0l : g_B1l;
    float* __restrict__ C = (L == 0) ? g_l0 : g_l1;

    int wid = threadIdx.x >> 5;
    int wm = blockIdx.x * (4 * WM * 16) + (wid >> 1) * (WM * 16);
    int wn = noff + (wid & 1) * (WN * 16);

    wmma::fragment<wmma::accumulator, 16, 16, 16, float> acc[WM][WN];
#pragma unroll
    for (int i = 0; i < WM; i++)
#pragma unroll
        for (int j = 0; j < WN; j++) wmma::fill_fragment(acc[i][j], 0.f);

    for (int kk = 0; kk < 128; kk += 16) {
        wmma::fragment<wmma::matrix_a, 16, 16, 16, __nv_bfloat16, wmma::row_major> ah[WM], al[WM];
        wmma::fragment<wmma::matrix_b, 16, 16, 16, __nv_bfloat16, wmma::col_major> bh[WN], bl[WN];
#pragma unroll
        for (int i = 0; i < WM; i++) {
            wmma::load_matrix_sync(ah[i], Ah + (size_t)(wm + i * 16) * 128 + kk, 128);
            wmma::load_matrix_sync(al[i], Al + (size_t)(wm + i * 16) * 128 + kk, 128);
        }
#pragma unroll
        for (int j = 0; j < WN; j++) {
            wmma::load_matrix_sync(bh[j], Bh + (size_t)(wn + j * 16) * 128 + kk, 128);
            wmma::load_matrix_sync(bl[j], Bl + (size_t)(wn + j * 16) * 128 + kk, 128);
        }
#pragma unroll
        for (int i = 0; i < WM; i++)
#pragma unroll
            for (int j = 0; j < WN; j++) {
                wmma::mma_sync(acc[i][j], ah[i], bh[j], acc[i][j]);
                wmma::mma_sync(acc[i][j], al[i], bh[j], acc[i][j]);
                wmma::mma_sync(acc[i][j], ah[i], bl[j], acc[i][j]);
            }
    }
#pragma unroll
    for (int i = 0; i < WM; i++)
#pragma unroll
        for (int j = 0; j < WN; j++)
            wmma::store_matrix_sync(C + (size_t)(wm + i * 16) * CS + wn + j * 16,
                                    acc[i][j], CS, wmma::mem_row_major);
}

// ---------------- attention logits ------------------------------------------
__global__ void k_att0(const float* __restrict__ as, const float* __restrict__ adw, int n) {
    int gw = (blockIdx.x * blockDim.x + threadIdx.x) >> 5;
    int lane = threadIdx.x & 31;
    if (gw >= n) return;
    float4 v  = *(const float4*)(g_l0 + (size_t)gw * 256 + lane * 4);
    float4 s4 = *(const float4*)(as + lane * 4);
    float4 d4 = *(const float4*)(adw + lane * 4);
    float s = v.x * s4.x + v.y * s4.y + v.z * s4.z + v.w * s4.w;
    float d = v.x * d4.x + v.y * d4.y + v.z * d4.z + v.w * d4.w;
#pragma unroll
    for (int o = 4; o; o >>= 1) {
        s += __shfl_down_sync(0xffffffffu, s, o, 8);
        d += __shfl_down_sync(0xffffffffu, d, o, 8);
    }
    if ((lane & 7) == 0) {
        int h = lane >> 3;
        g_as0[gw * 4 + h] = s;
        g_ad0[gw * 4 + h] = d;
    }
}

__global__ void k_att1(const float* __restrict__ as, const float* __restrict__ adw, int n) {
    int gw = (blockIdx.x * blockDim.x + threadIdx.x) >> 5;
    int lane = threadIdx.x & 31;
    if (gw >= n) return;
    float v = g_l1[(size_t)gw * 64 + lane];
    float s = v * as[lane];
    float d = v * adw[lane];
#pragma unroll
    for (int o = 16; o; o >>= 1) {
        s += __shfl_xor_sync(0xffffffffu, s, o);
        d += __shfl_xor_sync(0xffffffffu, d, o);
    }
    if (lane == 0) { g_as1[gw] = s; g_ad1[gw] = d; }
}

// ---------------- layer-0 aggregation: warp per dst node --------------------
// Output h is written directly as bf16 hi/lo (input for layer-1 GEMM).
__global__ void k_agg0(const float* __restrict__ bias0, const float* __restrict__ linb0, int n) {
    int gw = (blockIdx.x * blockDim.x + threadIdx.x) >> 5;
    int lane = threadIdx.x & 31;
    if (gw >= n) return;
    int beg = g_rowptr[gw], end = g_rowptr[gw + 1];
    float4 ad = *(const float4*)(g_ad0 + gw * 4);

    float mx0 = -1e30f, mx1 = -1e30f, mx2 = -1e30f, mx3 = -1e30f;
    for (int i = beg + lane; i < end; i += 32) {
        int s = g_csr_src[i];
        float4 av = *(const float4*)(g_as0 + s * 4);
        float e0 = av.x + ad.x; e0 = e0 > 0.f ? e0 : 0.2f * e0;
        float e1 = av.y + ad.y; e1 = e1 > 0.f ? e1 : 0.2f * e1;
        float e2 = av.z + ad.z; e2 = e2 > 0.f ? e2 : 0.2f * e2;
        float e3 = av.w + ad.w; e3 = e3 > 0.f ? e3 : 0.2f * e3;
        mx0 = fmaxf(mx0, e0); mx1 = fmaxf(mx1, e1);
        mx2 = fmaxf(mx2, e2); mx3 = fmaxf(mx3, e3);
    }
#pragma unroll
    for (int o = 16; o; o >>= 1) {
        mx0 = fmaxf(mx0, __shfl_xor_sync(0xffffffffu, mx0, o));
        mx1 = fmaxf(mx1, __shfl_xor_sync(0xffffffffu, mx1, o));
        mx2 = fmaxf(mx2, __shfl_xor_sync(0xffffffffu, mx2, o));
        mx3 = fmaxf(mx3, __shfl_xor_sync(0xffffffffu, mx3, o));
    }

    float dn0 = 0.f, dn1 = 0.f, dn2 = 0.f, dn3 = 0.f;
    for (int i = beg + lane; i < end; i += 32) {
        int s = g_csr_src[i];
        float4 av = *(const float4*)(g_as0 + s * 4);
        float e0 = av.x + ad.x; e0 = e0 > 0.f ? e0 : 0.2f * e0; dn0 += __expf(e0 - mx0);
        float e1 = av.y + ad.y; e1 = e1 > 0.f ? e1 : 0.2f * e1; dn1 += __expf(e1 - mx1);
        float e2 = av.z + ad.z; e2 = e2 > 0.f ? e2 : 0.2f * e2; dn2 += __expf(e2 - mx2);
        float e3 = av.w + ad.w; e3 = e3 > 0.f ? e3 : 0.2f * e3; dn3 += __expf(e3 - mx3);
    }
#pragma unroll
    for (int o = 16; o; o >>= 1) {
        dn0 += __shfl_xor_sync(0xffffffffu, dn0, o);
        dn1 += __shfl_xor_sync(0xffffffffu, dn1, o);
        dn2 += __shfl_xor_sync(0xffffffffu, dn2, o);
        dn3 += __shfl_xor_sync(0xffffffffu, dn3, o);
    }
    float inv0 = 1.f / (dn0 + 1e-16f);
    float inv1 = 1.f / (dn1 + 1e-16f);
    float inv2 = 1.f / (dn2 + 1e-16f);
    float inv3 = 1.f / (dn3 + 1e-16f);

    int   hsel  = lane & 3;
    float adsel = g_ad0[gw * 4 + hsel];
    float mxsel = (hsel == 0) ? mx0 : (hsel == 1) ? mx1 : (hsel == 2) ? mx2 : mx3;

    float acc0 = 0.f, acc1 = 0.f, acc2 = 0.f, acc3 = 0.f;
    for (int i = beg; i < end; i++) {
        int s = g_csr_src[i];
        float e = g_as0[s * 4 + hsel] + adsel;
        e = e > 0.f ? e : 0.2f * e;
        float we = __expf(e - mxsel);
        float w0 = __shfl_sync(0xffffffffu, we, 0);
        float w1 = __shfl_sync(0xffffffffu, we, 1);
        float w2 = __shfl_sync(0xffffffffu, we, 2);
        float w3 = __shfl_sync(0xffffffffu, we, 3);
        const float* row = g_l0 + (size_t)s * 256;
        acc0 = fmaf(w0, row[lane],      acc0);
        acc1 = fmaf(w1, row[32 + lane], acc1);
        acc2 = fmaf(w2, row[64 + lane], acc2);
        acc3 = fmaf(w3, row[96 + lane], acc3);
    }

    const float* skip = g_l0 + (size_t)gw * 256 + 128;
    float o0 = acc0 * inv0 + bias0[lane]      + linb0[lane]      + skip[lane];
    float o1 = acc1 * inv1 + bias0[32 + lane] + linb0[32 + lane] + skip[32 + lane];
    float o2 = acc2 * inv2 + bias0[64 + lane] + linb0[64 + lane] + skip[64 + lane];
    float o3 = acc3 * inv3 + bias0[96 + lane] + linb0[96 + lane] + skip[96 + lane];
    o0 = o0 > 0.f ? o0 : (__expf(o0) - 1.f);
    o1 = o1 > 0.f ? o1 : (__expf(o1) - 1.f);
    o2 = o2 > 0.f ? o2 : (__expf(o2) - 1.f);
    o3 = o3 > 0.f ? o3 : (__expf(o3) - 1.f);

    size_t rb = (size_t)gw * 128;
    __nv_bfloat16 h;
    h = __float2bfloat16_rn(o0); g_hh[rb + lane]      = h; g_hl[rb + lane]      = __float2bfloat16_rn(o0 - __bfloat162float(h));
    h = __float2bfloat16_rn(o1); g_hh[rb + 32 + lane] = h; g_hl[rb + 32 + lane] = __float2bfloat16_rn(o1 - __bfloat162float(h));
    h = __float2bfloat16_rn(o2); g_hh[rb + 64 + lane] = h; g_hl[rb + 64 + lane] = __float2bfloat16_rn(o2 - __bfloat162float(h));
    h = __float2bfloat16_rn(o3); g_hh[rb + 96 + lane] = h; g_hl[rb + 96 + lane] = __float2bfloat16_rn(o3 - __bfloat162float(h));
}

// ---------------- layer-1 aggregation: warp per dst node --------------------
__global__ void k_agg1(const float* __restrict__ bias1, const float* __restrict__ linb1,
                       float* __restrict__ out, int n) {
    int gw = (blockIdx.x * blockDim.x + threadIdx.x) >> 5;
    int lane = threadIdx.x & 31;
    if (gw >= n) return;
    int beg = g_rowptr[gw], end = g_rowptr[gw + 1];
    float ad = g_ad1[gw];

    float mx = -1e30f;
    for (int i = beg + lane; i < end; i += 32) {
        float e = g_as1[g_csr_src[i]] + ad;
        e = e > 0.f ? e : 0.2f * e;
        mx = fmaxf(mx, e);
    }
#pragma unroll
    for (int o = 16; o; o >>= 1) mx = fmaxf(mx, __shfl_xor_sync(0xffffffffu, mx, o));

    float dn = 0.f;
    for (int i = beg + lane; i < end; i += 32) {
        float e = g_as1[g_csr_src[i]] + ad;
        e = e > 0.f ? e : 0.2f * e;
        dn += __expf(e - mx);
    }
#pragma unroll
    for (int o = 16; o; o >>= 1) dn += __shfl_xor_sync(0xffffffffu, dn, o);
    float inv = 1.f / (dn + 1e-16f);

    float acc = 0.f;
    for (int i = beg; i < end; i++) {
        int s = g_csr_src[i];
        float e = g_as1[s] + ad;
        e = e > 0.f ? e : 0.2f * e;
        float we = __expf(e - mx);
        acc = fmaf(we, g_l1[(size_t)s * 64 + lane], acc);
    }
    out[(size_t)gw * 32 + lane] =
        acc * inv + bias1[lane] + linb1[lane] + g_l1[(size_t)gw * 64 + 32 + lane];
}

// ---------------- launcher ---------------------------------------------------
extern "C" void kernel_launch(void* const* d_in, const int* in_sizes, int n_in,
                              void* d_out, int out_size) {
    const float* x   = (const float*)d_in[0];
    const int*   ei  = (const int*)  d_in[1];
    const float* W0  = (const float*)d_in[2];
    const float* as0 = (const float*)d_in[3];
    const float* ad0 = (const float*)d_in[4];
    const float* b0  = (const float*)d_in[5];
    const float* lW0 = (const float*)d_in[6];
    const float* lb0 = (const float*)d_in[7];
    const float* W1  = (const float*)d_in[8];
    const float* as1 = (const float*)d_in[9];
    const float* ad1 = (const float*)d_in[10];
    const float* b1  = (const float*)d_in[11];
    const float* lW1 = (const float*)d_in[12];
    const float* lb1 = (const float*)d_in[13];
    float* out = (float*)d_out;

    int n = in_sizes[0] / 128;
    int e = in_sizes[1] / 2;
    int etot = n + e;
    int nb = (n + SCAN_BS - 1) / SCAN_BS;
    int ntiles = (n + 127) / 128;            // 391 row tiles of 128
    int nquads = n * 32;                     // float4 quads in x

    // weights + x prep, CSR build
    k_prep<<<(128 * 128 + 255) / 256, 256>>>(W0, lW0, W1, lW1);
    k_split<<<(nquads + 255) / 256, 256>>>(x, nquads);
    k_zero_deg<<<(n + 255) / 256, 256>>>(n);
    k_hist<<<(etot + 255) / 256, 256>>>(ei, e, etot);
    k_scan1<<<nb, SCAN_BS>>>(n);
    k_scan2<<<1, SCAN_BS>>>(nb);
    k_scan3<<<(n + 255) / 256, 256>>>(n);
    k_scatter<<<(etot + 255) / 256, 256>>>(ei, e, etot);

    // layer 0: WMMA GEMM in two 128-col slabs, then logits + aggregation
    k_wmma<0, 2, 4, 256><<<ntiles, 256>>>(0);
    k_wmma<0, 2, 4, 256><<<ntiles, 256>>>(128);
    k_att0<<<(n + 7) / 8, 256>>>(as0, ad0, n);
    k_agg0<<<(n + 7) / 8, 256>>>(b0, lb0, n);

    // layer 1
    k_wmma<1, 2, 2, 64><<<ntiles, 256>>>(0);
    k_att1<<<(n + 7) / 8, 256>>>(as1, ad1, n);
    k_agg1<<<(n + 7) / 8, 256>>>(b1, lb1, out, n);
}

// round 7
// speedup vs baseline: 1.2324x; 1.1940x over previous
#include <cuda_runtime.h>
#include <cuda_bf16.h>
#include <cstdint>

// ---------------- problem-size constants (fixed by the reference) ----------
#define NNODES   50000
#define NPAD     50048                  // padded to multiple of 128
#define NEDGES   800000
#define ETOT     (NNODES + NEDGES)      // 850000 (edges + self loops)
#define SCAN_BS  512

// ---------------- device scratch (no allocations allowed) ------------------
// ONLY referenced from device code (host-side use of a __device__ symbol as a
// kernel arg silently reads the host shadow via ATS -> zero output).
__device__ float g_l0[(size_t)NPAD * 256];   // [x@W0^T | x@linW0^T]
__device__ float g_l1[(size_t)NPAD * 64];    // [h@W1^T | h@linW1^T]
__device__ __nv_bfloat16 g_xh[(size_t)NPAD * 128];
__device__ __nv_bfloat16 g_xl[(size_t)NPAD * 128];
__device__ __nv_bfloat16 g_hh[(size_t)NPAD * 128];
__device__ __nv_bfloat16 g_hl[(size_t)NPAD * 128];
__device__ float g_as0[NNODES * 4];
__device__ float g_ad0[NNODES * 4];
__device__ float g_as1[NNODES];
__device__ float g_ad1[NNODES];
__device__ int   g_deg[NNODES + 64];
__device__ int   g_rowtmp[NNODES + 64];
__device__ int   g_rowptr[NNODES + 64];
__device__ int   g_cursor[NNODES + 64];
__device__ int   g_csr_src[ETOT + 64];
__device__ int   g_bsum[SCAN_BS];
__device__ int   g_boff[SCAN_BS];
__device__ __nv_bfloat16 g_B0h[256 * 128];
__device__ __nv_bfloat16 g_B0l[256 * 128];
__device__ __nv_bfloat16 g_B1h[64 * 128];
__device__ __nv_bfloat16 g_B1l[64 * 128];

// ---------------- helpers ---------------------------------------------------
__device__ __forceinline__ uint32_t smem_u32(const void* p) {
    uint32_t a;
    asm("{ .reg .u64 t; cvta.to.shared.u64 t, %1; cvt.u32.u64 %0, t; }" : "=r"(a) : "l"(p));
    return a;
}
__device__ __forceinline__ void ldsm_x4(uint32_t* r, uint32_t addr) {
    asm volatile("ldmatrix.sync.aligned.m8n8.x4.shared.b16 {%0,%1,%2,%3}, [%4];"
                 : "=r"(r[0]), "=r"(r[1]), "=r"(r[2]), "=r"(r[3]) : "r"(addr));
}
__device__ __forceinline__ void ldsm_x2(uint32_t* r, uint32_t addr) {
    asm volatile("ldmatrix.sync.aligned.m8n8.x2.shared.b16 {%0,%1}, [%2];"
                 : "=r"(r[0]), "=r"(r[1]) : "r"(addr));
}
__device__ __forceinline__ void mma_bf16(float* d, const uint32_t* a, const uint32_t* b) {
    asm volatile(
        "mma.sync.aligned.m16n8k16.row.col.f32.bf16.bf16.f32 "
        "{%0,%1,%2,%3}, {%4,%5,%6,%7}, {%8,%9}, {%0,%1,%2,%3};"
        : "+f"(d[0]), "+f"(d[1]), "+f"(d[2]), "+f"(d[3])
        : "r"(a[0]), "r"(a[1]), "r"(a[2]), "r"(a[3]), "r"(b[0]), "r"(b[1]));
}

// ---------------- weight prep: fp32 -> bf16 hi/lo ---------------------------
__global__ void k_prep(const float* __restrict__ W0, const float* __restrict__ lW0,
                       const float* __restrict__ W1, const float* __restrict__ lW1) {
    int i = blockIdx.x * blockDim.x + threadIdx.x;
    if (i < 128 * 128) {
        float v = W0[i];
        __nv_bfloat16 h = __float2bfloat16_rn(v);
        g_B0h[i] = h; g_B0l[i] = __float2bfloat16_rn(v - __bfloat162float(h));
        v = lW0[i];
        h = __float2bfloat16_rn(v);
        g_B0h[128 * 128 + i] = h; g_B0l[128 * 128 + i] = __float2bfloat16_rn(v - __bfloat162float(h));
    }
    if (i < 32 * 128) {
        float v = W1[i];
        __nv_bfloat16 h = __float2bfloat16_rn(v);
        g_B1h[i] = h; g_B1l[i] = __float2bfloat16_rn(v - __bfloat162float(h));
        v = lW1[i];
        h = __float2bfloat16_rn(v);
        g_B1h[32 * 128 + i] = h; g_B1l[32 * 128 + i] = __float2bfloat16_rn(v - __bfloat162float(h));
    }
}

// ---------------- x prep: fp32 -> bf16 hi/lo ---------------------------------
__global__ void k_split(const float* __restrict__ src, int nquads) {
    int i = blockIdx.x * blockDim.x + threadIdx.x;
    if (i >= nquads) return;
    float4 v = ((const float4*)src)[i];
    __nv_bfloat16 hx = __float2bfloat16_rn(v.x), hy = __float2bfloat16_rn(v.y);
    __nv_bfloat16 hz = __float2bfloat16_rn(v.z), hw = __float2bfloat16_rn(v.w);
    int b = i * 4;
    g_xh[b]     = hx; g_xl[b]     = __float2bfloat16_rn(v.x - __bfloat162float(hx));
    g_xh[b + 1] = hy; g_xl[b + 1] = __float2bfloat16_rn(v.y - __bfloat162float(hy));
    g_xh[b + 2] = hz; g_xl[b + 2] = __float2bfloat16_rn(v.z - __bfloat162float(hz));
    g_xh[b + 3] = hw; g_xl[b + 3] = __float2bfloat16_rn(v.w - __bfloat162float(hw));
}

// ---------------- CSR build -------------------------------------------------
__global__ void k_zero_deg(int n) {
    int i = blockIdx.x * blockDim.x + threadIdx.x;
    if (i < n) g_deg[i] = 0;
}
__global__ void k_hist(const int* __restrict__ ei, int e, int etot) {
    int k = blockIdx.x * blockDim.x + threadIdx.x;
    if (k >= etot) return;
    int dst = (k < e) ? ei[e + k] : (k - e);
    atomicAdd(&g_deg[dst], 1);
}
__global__ void k_scan1(int n) {
    __shared__ int sh[SCAN_BS];
    int t = threadIdx.x;
    int i = blockIdx.x * SCAN_BS + t;
    int v = (i < n) ? g_deg[i] : 0;
    sh[t] = v;
    __syncthreads();
    for (int o = 1; o < SCAN_BS; o <<= 1) {
        int x = (t >= o) ? sh[t - o] : 0;
        __syncthreads();
        sh[t] += x;
        __syncthreads();
    }
    if (i < n) g_rowtmp[i] = sh[t];
    if (t == SCAN_BS - 1) g_bsum[blockIdx.x] = sh[t];
}
__global__ void k_scan2(int nb) {
    __shared__ int sh[SCAN_BS];
    int t = threadIdx.x;
    int v = (t < nb) ? g_bsum[t] : 0;
    sh[t] = v;
    __syncthreads();
    for (int o = 1; o < SCAN_BS; o <<= 1) {
        int x = (t >= o) ? sh[t - o] : 0;
        __syncthreads();
        sh[t] += x;
        __syncthreads();
    }
    if (t < nb) g_boff[t] = sh[t] - v;
}
__global__ void k_scan3(int n) {
    int i = blockIdx.x * blockDim.x + threadIdx.x;
    if (i >= n) return;
    int incl = g_rowtmp[i] + g_boff[i >> 9];
    g_rowptr[i + 1] = incl;
    g_cursor[i] = incl - g_deg[i];
    if (i == 0) g_rowptr[0] = 0;
}
__global__ void k_scatter(const int* __restrict__ ei, int e, int etot) {
    int k = blockIdx.x * blockDim.x + threadIdx.x;
    if (k >= etot) return;
    int src, dst;
    if (k < e) { src = ei[k]; dst = ei[e + k]; }
    else       { src = dst = k - e; }
    int pos = atomicAdd(&g_cursor[dst], 1);
    g_csr_src[pos] = src;
}

// ---------------- HMMA GEMM + fused attention logits -------------------------
// C[:, noff..noff+NN] = A[M,128] * B[noff.., 128]^T via smem + ldmatrix + mma.
// fp32 via 3-product bf16 split (Ah*Bh + Al*Bh + Ah*Bl), fp32 reg accum.
// L=0: A=g_xh/xl, B=g_B0h/l, C=g_l0 (CS=256, NN=128 slabs via blockIdx.y).
// L=1: A=g_hh/hl, B=g_B1h/l, C=g_l1 (CS=64, NN=64).
// The h-columns (noff==0) also produce a_src/a_dst logits in the epilogue.
template <int L, int NN, int CS>
__global__ void __launch_bounds__(256) k_mma(
    const float* __restrict__ attS, const float* __restrict__ attD, int M)
{
    constexpr int WNN = (NN == 128) ? 4 : 2;   // warps along n
    constexpr int WMN = 8 / WNN;               // warps along m
    constexpr int WARP_M = 128 / WMN;          // 64 or 32
    constexpr int WARP_N = 32;                 // one head per warp
    constexpr int MI = WARP_M / 16;            // 4 or 2
    constexpr int NI = WARP_N / 8;             // 4
    constexpr int PB = 272;                    // pitch bytes (17*16B -> conflict-free)
    constexpr int SM_AHI = 0;
    constexpr int SM_ALO = 128 * PB;
    constexpr int SM_BHI = 2 * 128 * PB;
    constexpr int SM_BLO = SM_BHI + NN * PB;

    const __nv_bfloat16* __restrict__ Ah = (L == 0) ? g_xh : g_hh;
    const __nv_bfloat16* __restrict__ Al = (L == 0) ? g_xl : g_hl;
    const __nv_bfloat16* __restrict__ Bh = (L == 0) ? g_B0h : g_B1h;
    const __nv_bfloat16* __restrict__ Bl = (L == 0) ? g_B0l : g_B1l;
    float* __restrict__ C = (L == 0) ? g_l0 : g_l1;

    extern __shared__ char smem[];
    uint32_t sb = smem_u32(smem);
    int tid = threadIdx.x, wid = tid >> 5, lane = tid & 31;
    int base = blockIdx.x * 128;
    int noff = blockIdx.y * NN;

    // ---- stage B slab (bf16 hi/lo)
    for (int idx = tid; idx < NN * 16; idx += 256) {
        int row = idx >> 4, q = idx & 15;
        *(uint4*)(smem + SM_BHI + row * PB + q * 16) = *(const uint4*)(Bh + (size_t)(noff + row) * 128 + q * 8);
        *(uint4*)(smem + SM_BLO + row * PB + q * 16) = *(const uint4*)(Bl + (size_t)(noff + row) * 128 + q * 8);
    }
    // ---- stage A (bf16 hi/lo, rows >= M are zero in the padded globals)
    for (int idx = tid; idx < 128 * 16; idx += 256) {
        int row = idx >> 4, q = idx & 15;
        *(uint4*)(smem + SM_AHI + row * PB + q * 16) = *(const uint4*)(Ah + (size_t)(base + row) * 128 + q * 8);
        *(uint4*)(smem + SM_ALO + row * PB + q * 16) = *(const uint4*)(Al + (size_t)(base + row) * 128 + q * 8);
    }
    __syncthreads();

    int wm = (wid / WNN) * WARP_M;
    int wn = (wid % WNN) * WARP_N;          // smem-local col offset

    uint32_t a_off = (uint32_t)((wm + (lane & 15)) * PB + (lane >> 4) * 16);
    uint32_t b_off = (uint32_t)((wn + (lane & 7)) * PB + (((lane & 15) >> 3)) * 16);

    float acc[MI][NI][4];
#pragma unroll
    for (int mi = 0; mi < MI; mi++)
#pragma unroll
        for (int ni = 0; ni < NI; ni++)
#pragma unroll
            for (int r = 0; r < 4; r++) acc[mi][ni][r] = 0.f;

#pragma unroll
    for (int p = 0; p < 3; p++) {
        uint32_t abase = sb + ((p == 1) ? SM_ALO : SM_AHI) + a_off;
        uint32_t bbase = sb + ((p == 2) ? SM_BLO : SM_BHI) + b_off;
#pragma unroll
        for (int ks = 0; ks < 8; ks++) {
            uint32_t a[MI][4], b[NI][2];
#pragma unroll
            for (int mi = 0; mi < MI; mi++)
                ldsm_x4(a[mi], abase + mi * 16 * PB + ks * 32);
#pragma unroll
            for (int ni = 0; ni < NI; ni++)
                ldsm_x2(b[ni], bbase + ni * 8 * PB + ks * 32);
#pragma unroll
            for (int mi = 0; mi < MI; mi++)
#pragma unroll
                for (int ni = 0; ni < NI; ni++)
                    mma_bf16(acc[mi][ni], a[mi], b[ni]);
        }
    }

    // ---- C store: d0,d1 -> (row g, col tg*2..+1); d2,d3 -> row g+8
    int g = lane >> 2, tg = lane & 3;
#pragma unroll
    for (int mi = 0; mi < MI; mi++) {
        int r0 = base + wm + mi * 16 + g;
#pragma unroll
        for (int ni = 0; ni < NI; ni++) {
            int col = noff + wn + ni * 8 + tg * 2;
            *(float2*)(C + (size_t)r0 * CS + col)       = make_float2(acc[mi][ni][0], acc[mi][ni][1]);
            *(float2*)(C + (size_t)(r0 + 8) * CS + col) = make_float2(acc[mi][ni][2], acc[mi][ni][3]);
        }
    }

    // ---- fused attention logits (h-columns only: noff==0)
    if (noff == 0) {
        int head = wid % WNN;               // 32-col group = one head (L0), head0 (L1)
        if (L == 1 && head != 0) return;
        float s_w[NI * 2], d_w[NI * 2];
#pragma unroll
        for (int ni = 0; ni < NI; ni++) {
            int ci = ni * 8 + tg * 2;
            s_w[ni * 2]     = __ldg(attS + head * 32 + ci);
            s_w[ni * 2 + 1] = __ldg(attS + head * 32 + ci + 1);
            d_w[ni * 2]     = __ldg(attD + head * 32 + ci);
            d_w[ni * 2 + 1] = __ldg(attD + head * 32 + ci + 1);
        }
#pragma unroll
        for (int mi = 0; mi < MI; mi++) {
            float s0 = 0.f, d0 = 0.f, s1 = 0.f, d1 = 0.f;
#pragma unroll
            for (int ni = 0; ni < NI; ni++) {
                s0 = fmaf(acc[mi][ni][0], s_w[ni * 2], fmaf(acc[mi][ni][1], s_w[ni * 2 + 1], s0));
                d0 = fmaf(acc[mi][ni][0], d_w[ni * 2], fmaf(acc[mi][ni][1], d_w[ni * 2 + 1], d0));
                s1 = fmaf(acc[mi][ni][2], s_w[ni * 2], fmaf(acc[mi][ni][3], s_w[ni * 2 + 1], s1));
                d1 = fmaf(acc[mi][ni][2], d_w[ni * 2], fmaf(acc[mi][ni][3], d_w[ni * 2 + 1], d1));
            }
#pragma unroll
            for (int o = 1; o <= 2; o <<= 1) {
                s0 += __shfl_xor_sync(0xffffffffu, s0, o);
                d0 += __shfl_xor_sync(0xffffffffu, d0, o);
                s1 += __shfl_xor_sync(0xffffffffu, s1, o);
                d1 += __shfl_xor_sync(0xffffffffu, d1, o);
            }
            if (tg == 0) {
                int r0 = base + wm + mi * 16 + g;
                int r1 = r0 + 8;
                if (L == 0) {
                    if (r0 < M) { g_as0[r0 * 4 + head] = s0; g_ad0[r0 * 4 + head] = d0; }
                    if (r1 < M) { g_as0[r1 * 4 + head] = s1; g_ad0[r1 * 4 + head] = d1; }
                } else {
                    if (r0 < M) { g_as1[r0] = s0; g_ad1[r0] = d0; }
                    if (r1 < M) { g_as1[r1] = s1; g_ad1[r1] = d1; }
                }
            }
        }
    }
}

// ---------------- layer-0 aggregation: warp per dst node --------------------
// Output h written directly as bf16 hi/lo (input of layer-1 GEMM).
__global__ void k_agg0(const float* __restrict__ bias0, const float* __restrict__ linb0, int n) {
    int gw = (blockIdx.x * blockDim.x + threadIdx.x) >> 5;
    int lane = threadIdx.x & 31;
    if (gw >= n) return;
    int beg = g_rowptr[gw], end = g_rowptr[gw + 1];
    float4 ad = *(const float4*)(g_ad0 + gw * 4);

    float mx0 = -1e30f, mx1 = -1e30f, mx2 = -1e30f, mx3 = -1e30f;
    for (int i = beg + lane; i < end; i += 32) {
        int s = g_csr_src[i];
        float4 av = *(const float4*)(g_as0 + s * 4);
        float e0 = av.x + ad.x; e0 = e0 > 0.f ? e0 : 0.2f * e0;
        float e1 = av.y + ad.y; e1 = e1 > 0.f ? e1 : 0.2f * e1;
        float e2 = av.z + ad.z; e2 = e2 > 0.f ? e2 : 0.2f * e2;
        float e3 = av.w + ad.w; e3 = e3 > 0.f ? e3 : 0.2f * e3;
        mx0 = fmaxf(mx0, e0); mx1 = fmaxf(mx1, e1);
        mx2 = fmaxf(mx2, e2); mx3 = fmaxf(mx3, e3);
    }
#pragma unroll
    for (int o = 16; o; o >>= 1) {
        mx0 = fmaxf(mx0, __shfl_xor_sync(0xffffffffu, mx0, o));
        mx1 = fmaxf(mx1, __shfl_xor_sync(0xffffffffu, mx1, o));
        mx2 = fmaxf(mx2, __shfl_xor_sync(0xffffffffu, mx2, o));
        mx3 = fmaxf(mx3, __shfl_xor_sync(0xffffffffu, mx3, o));
    }

    float dn0 = 0.f, dn1 = 0.f, dn2 = 0.f, dn3 = 0.f;
    for (int i = beg + lane; i < end; i += 32) {
        int s = g_csr_src[i];
        float4 av = *(const float4*)(g_as0 + s * 4);
        float e0 = av.x + ad.x; e0 = e0 > 0.f ? e0 : 0.2f * e0; dn0 += __expf(e0 - mx0);
        float e1 = av.y + ad.y; e1 = e1 > 0.f ? e1 : 0.2f * e1; dn1 += __expf(e1 - mx1);
        float e2 = av.z + ad.z; e2 = e2 > 0.f ? e2 : 0.2f * e2; dn2 += __expf(e2 - mx2);
        float e3 = av.w + ad.w; e3 = e3 > 0.f ? e3 : 0.2f * e3; dn3 += __expf(e3 - mx3);
    }
#pragma unroll
    for (int o = 16; o; o >>= 1) {
        dn0 += __shfl_xor_sync(0xffffffffu, dn0, o);
        dn1 += __shfl_xor_sync(0xffffffffu, dn1, o);
        dn2 += __shfl_xor_sync(0xffffffffu, dn2, o);
        dn3 += __shfl_xor_sync(0xffffffffu, dn3, o);
    }
    float inv0 = 1.f / (dn0 + 1e-16f);
    float inv1 = 1.f / (dn1 + 1e-16f);
    float inv2 = 1.f / (dn2 + 1e-16f);
    float inv3 = 1.f / (dn3 + 1e-16f);

    int   hsel  = lane & 3;
    float adsel = g_ad0[gw * 4 + hsel];
    float mxsel = (hsel == 0) ? mx0 : (hsel == 1) ? mx1 : (hsel == 2) ? mx2 : mx3;

    float acc0 = 0.f, acc1 = 0.f, acc2 = 0.f, acc3 = 0.f;
    for (int i = beg; i < end; i++) {
        int s = g_csr_src[i];
        float e = g_as0[s * 4 + hsel] + adsel;
        e = e > 0.f ? e : 0.2f * e;
        float we = __expf(e - mxsel);
        float w0 = __shfl_sync(0xffffffffu, we, 0);
        float w1 = __shfl_sync(0xffffffffu, we, 1);
        float w2 = __shfl_sync(0xffffffffu, we, 2);
        float w3 = __shfl_sync(0xffffffffu, we, 3);
        const float* row = g_l0 + (size_t)s * 256;
        acc0 = fmaf(w0, row[lane],      acc0);
        acc1 = fmaf(w1, row[32 + lane], acc1);
        acc2 = fmaf(w2, row[64 + lane], acc2);
        acc3 = fmaf(w3, row[96 + lane], acc3);
    }

    const float* skip = g_l0 + (size_t)gw * 256 + 128;
    float o0 = acc0 * inv0 + bias0[lane]      + linb0[lane]      + skip[lane];
    float o1 = acc1 * inv1 + bias0[32 + lane] + linb0[32 + lane] + skip[32 + lane];
    float o2 = acc2 * inv2 + bias0[64 + lane] + linb0[64 + lane] + skip[64 + lane];
    float o3 = acc3 * inv3 + bias0[96 + lane] + linb0[96 + lane] + skip[96 + lane];
    o0 = o0 > 0.f ? o0 : (__expf(o0) - 1.f);
    o1 = o1 > 0.f ? o1 : (__expf(o1) - 1.f);
    o2 = o2 > 0.f ? o2 : (__expf(o2) - 1.f);
    o3 = o3 > 0.f ? o3 : (__expf(o3) - 1.f);

    size_t rb = (size_t)gw * 128;
    __nv_bfloat16 h;
    h = __float2bfloat16_rn(o0); g_hh[rb + lane]      = h; g_hl[rb + lane]      = __float2bfloat16_rn(o0 - __bfloat162float(h));
    h = __float2bfloat16_rn(o1); g_hh[rb + 32 + lane] = h; g_hl[rb + 32 + lane] = __float2bfloat16_rn(o1 - __bfloat162float(h));
    h = __float2bfloat16_rn(o2); g_hh[rb + 64 + lane] = h; g_hl[rb + 64 + lane] = __float2bfloat16_rn(o2 - __bfloat162float(h));
    h = __float2bfloat16_rn(o3); g_hh[rb + 96 + lane] = h; g_hl[rb + 96 + lane] = __float2bfloat16_rn(o3 - __bfloat162float(h));
}

// ---------------- layer-1 aggregation: warp per dst node --------------------
__global__ void k_agg1(const float* __restrict__ bias1, const float* __restrict__ linb1,
                       float* __restrict__ out, int n) {
    int gw = (blockIdx.x * blockDim.x + threadIdx.x) >> 5;
    int lane = threadIdx.x & 31;
    if (gw >= n) return;
    int beg = g_rowptr[gw], end = g_rowptr[gw + 1];
    float ad = g_ad1[gw];

    float mx = -1e30f;
    for (int i = beg + lane; i < end; i += 32) {
        float e = g_as1[g_csr_src[i]] + ad;
        e = e > 0.f ? e : 0.2f * e;
        mx = fmaxf(mx, e);
    }
#pragma unroll
    for (int o = 16; o; o >>= 1) mx = fmaxf(mx, __shfl_xor_sync(0xffffffffu, mx, o));

    float dn = 0.f;
    for (int i = beg + lane; i < end; i += 32) {
        float e = g_as1[g_csr_src[i]] + ad;
        e = e > 0.f ? e : 0.2f * e;
        dn += __expf(e - mx);
    }
#pragma unroll
    for (int o = 16; o; o >>= 1) dn += __shfl_xor_sync(0xffffffffu, dn, o);
    float inv = 1.f / (dn + 1e-16f);

    float acc = 0.f;
    for (int i = beg; i < end; i++) {
        int s = g_csr_src[i];
        float e = g_as1[s] + ad;
        e = e > 0.f ? e : 0.2f * e;
        float we = __expf(e - mx);
        acc = fmaf(we, g_l1[(size_t)s * 64 + lane], acc);
    }
    out[(size_t)gw * 32 + lane] =
        acc * inv + bias1[lane] + linb1[lane] + g_l1[(size_t)gw * 64 + 32 + lane];
}

// ---------------- launcher ---------------------------------------------------
extern "C" void kernel_launch(void* const* d_in, const int* in_sizes, int n_in,
                              void* d_out, int out_size) {
    const float* x   = (const float*)d_in[0];
    const int*   ei  = (const int*)  d_in[1];
    const float* W0  = (const float*)d_in[2];
    const float* as0 = (const float*)d_in[3];
    const float* ad0 = (const float*)d_in[4];
    const float* b0  = (const float*)d_in[5];
    const float* lW0 = (const float*)d_in[6];
    const float* lb0 = (const float*)d_in[7];
    const float* W1  = (const float*)d_in[8];
    const float* as1 = (const float*)d_in[9];
    const float* ad1 = (const float*)d_in[10];
    const float* b1  = (const float*)d_in[11];
    const float* lW1 = (const float*)d_in[12];
    const float* lb1 = (const float*)d_in[13];
    float* out = (float*)d_out;

    int n = in_sizes[0] / 128;
    int e = in_sizes[1] / 2;
    int etot = n + e;
    int nb = (n + SCAN_BS - 1) / SCAN_BS;
    int ntiles = (n + 127) / 128;
    int nquads = n * 32;

    const int smem0 = 2 * 128 * 272 + 2 * 128 * 272;  // 139264
    const int smem1 = 2 * 128 * 272 + 2 * 64 * 272;   // 104448
    cudaFuncSetAttribute(k_mma<0, 128, 256>, cudaFuncAttributeMaxDynamicSharedMemorySize, smem0);
    cudaFuncSetAttribute(k_mma<1, 64, 64>,   cudaFuncAttributeMaxDynamicSharedMemorySize, smem1);

    // weights + x prep, CSR build
    k_prep<<<(128 * 128 + 255) / 256, 256>>>(W0, lW0, W1, lW1);
    k_split<<<(nquads + 255) / 256, 256>>>(x, nquads);
    k_zero_deg<<<(n + 255) / 256, 256>>>(n);
    k_hist<<<(etot + 255) / 256, 256>>>(ei, e, etot);
    k_scan1<<<nb, SCAN_BS>>>(n);
    k_scan2<<<1, SCAN_BS>>>(nb);
    k_scan3<<<(n + 255) / 256, 256>>>(n);
    k_scatter<<<(etot + 255) / 256, 256>>>(ei, e, etot);

    // layer 0: HMMA GEMM (2 slabs; slab0 fuses a_src/a_dst), then aggregation
    k_mma<0, 128, 256><<<dim3(ntiles, 2), 256, smem0>>>(as0, ad0, n);
    k_agg0<<<(n + 7) / 8, 256>>>(b0, lb0, n);

    // layer 1: HMMA GEMM (fused logits), then aggregation
    k_mma<1, 64, 64><<<dim3(ntiles, 1), 256, smem1>>>(as1, ad1, n);
    k_agg1<<<(n + 7) / 8, 256>>>(b1, lb1, out, n);
}

// round 8
// speedup vs baseline: 1.3616x; 1.1049x over previous
#include <cuda_runtime.h>
#include <cuda_bf16.h>
#include <cstdint>

// ---------------- problem-size constants (fixed by the reference) ----------
#define NNODES   50000
#define NPAD     50048                  // padded to multiple of 128
#define NEDGES   800000
#define ETOT     (NNODES + NEDGES)      // 850000 (edges + self loops)
#define SCAN_BS  512

// ---------------- device scratch (no allocations allowed) ------------------
// ONLY referenced from device code (host-side use of a __device__ symbol as a
// kernel arg silently reads the host shadow via ATS -> zero output).
__device__ float g_l0[(size_t)NPAD * 256];   // [x@W0^T | x@linW0^T]
__device__ float g_l1[(size_t)NPAD * 64];    // [h@W1^T | h@linW1^T]
__device__ __nv_bfloat16 g_hh[(size_t)NPAD * 128];
__device__ __nv_bfloat16 g_hl[(size_t)NPAD * 128];
__device__ float g_as0[NNODES * 4];
__device__ float g_ad0[NNODES * 4];
__device__ float g_as1[NNODES];
__device__ float g_ad1[NNODES];
__device__ int   g_deg[NNODES + 64];
__device__ int   g_rowtmp[NNODES + 64];
__device__ int   g_rowptr[NNODES + 64];
__device__ int   g_cursor[NNODES + 64];
__device__ int   g_csr_src[ETOT + 64];
__device__ int   g_bsum[SCAN_BS];
__device__ int   g_boff[SCAN_BS];
__device__ __nv_bfloat16 g_B0h[256 * 128];
__device__ __nv_bfloat16 g_B0l[256 * 128];
__device__ __nv_bfloat16 g_B1h[64 * 128];
__device__ __nv_bfloat16 g_B1l[64 * 128];

// ---------------- helpers ---------------------------------------------------
__device__ __forceinline__ uint32_t smem_u32(const void* p) {
    uint32_t a;
    asm("{ .reg .u64 t; cvta.to.shared.u64 t, %1; cvt.u32.u64 %0, t; }" : "=r"(a) : "l"(p));
    return a;
}
__device__ __forceinline__ void ldsm_x4(uint32_t* r, uint32_t addr) {
    asm volatile("ldmatrix.sync.aligned.m8n8.x4.shared.b16 {%0,%1,%2,%3}, [%4];"
                 : "=r"(r[0]), "=r"(r[1]), "=r"(r[2]), "=r"(r[3]) : "r"(addr));
}
__device__ __forceinline__ void ldsm_x2(uint32_t* r, uint32_t addr) {
    asm volatile("ldmatrix.sync.aligned.m8n8.x2.shared.b16 {%0,%1}, [%2];"
                 : "=r"(r[0]), "=r"(r[1]) : "r"(addr));
}
__device__ __forceinline__ void mma_bf16(float* d, const uint32_t* a, const uint32_t* b) {
    asm volatile(
        "mma.sync.aligned.m16n8k16.row.col.f32.bf16.bf16.f32 "
        "{%0,%1,%2,%3}, {%4,%5,%6,%7}, {%8,%9}, {%0,%1,%2,%3};"
        : "+f"(d[0]), "+f"(d[1]), "+f"(d[2]), "+f"(d[3])
        : "r"(a[0]), "r"(a[1]), "r"(a[2]), "r"(a[3]), "r"(b[0]), "r"(b[1]));
}

// ---------------- setup: weight split + degree zero -------------------------
__global__ void k_setup(const float* __restrict__ W0, const float* __restrict__ lW0,
                        const float* __restrict__ W1, const float* __restrict__ lW1, int n) {
    int i = blockIdx.x * blockDim.x + threadIdx.x;
    if (i < 128 * 128) {
        float v = W0[i];
        __nv_bfloat16 h = __float2bfloat16_rn(v);
        g_B0h[i] = h; g_B0l[i] = __float2bfloat16_rn(v - __bfloat162float(h));
        v = lW0[i];
        h = __float2bfloat16_rn(v);
        g_B0h[128 * 128 + i] = h; g_B0l[128 * 128 + i] = __float2bfloat16_rn(v - __bfloat162float(h));
    }
    if (i < 32 * 128) {
        float v = W1[i];
        __nv_bfloat16 h = __float2bfloat16_rn(v);
        g_B1h[i] = h; g_B1l[i] = __float2bfloat16_rn(v - __bfloat162float(h));
        v = lW1[i];
        h = __float2bfloat16_rn(v);
        g_B1h[32 * 128 + i] = h; g_B1l[32 * 128 + i] = __float2bfloat16_rn(v - __bfloat162float(h));
    }
    if (i < n) g_deg[i] = 0;
}

// ---------------- CSR build -------------------------------------------------
__global__ void k_hist(const int* __restrict__ ei, int e, int etot) {
    int k = blockIdx.x * blockDim.x + threadIdx.x;
    if (k >= etot) return;
    int dst = (k < e) ? ei[e + k] : (k - e);
    atomicAdd(&g_deg[dst], 1);
}
__global__ void k_scan1(int n) {
    __shared__ int sh[SCAN_BS];
    int t = threadIdx.x;
    int i = blockIdx.x * SCAN_BS + t;
    int v = (i < n) ? g_deg[i] : 0;
    sh[t] = v;
    __syncthreads();
    for (int o = 1; o < SCAN_BS; o <<= 1) {
        int x = (t >= o) ? sh[t - o] : 0;
        __syncthreads();
        sh[t] += x;
        __syncthreads();
    }
    if (i < n) g_rowtmp[i] = sh[t];
    if (t == SCAN_BS - 1) g_bsum[blockIdx.x] = sh[t];
}
__global__ void k_scan2(int nb) {
    __shared__ int sh[SCAN_BS];
    int t = threadIdx.x;
    int v = (t < nb) ? g_bsum[t] : 0;
    sh[t] = v;
    __syncthreads();
    for (int o = 1; o < SCAN_BS; o <<= 1) {
        int x = (t >= o) ? sh[t - o] : 0;
        __syncthreads();
        sh[t] += x;
        __syncthreads();
    }
    if (t < nb) g_boff[t] = sh[t] - v;
}
__global__ void k_scan3(int n) {
    int i = blockIdx.x * blockDim.x + threadIdx.x;
    if (i >= n) return;
    int incl = g_rowtmp[i] + g_boff[i >> 9];
    g_rowptr[i + 1] = incl;
    g_cursor[i] = incl - g_deg[i];
    if (i == 0) g_rowptr[0] = 0;
}
__global__ void k_scatter(const int* __restrict__ ei, int e, int etot) {
    int k = blockIdx.x * blockDim.x + threadIdx.x;
    if (k >= etot) return;
    int src, dst;
    if (k < e) { src = ei[k]; dst = ei[e + k]; }
    else       { src = dst = k - e; }
    int pos = atomicAdd(&g_cursor[dst], 1);
    g_csr_src[pos] = src;
}

// ---------------- HMMA GEMM + fused attention logits -------------------------
// C[:, noff..noff+NN] = A[M,128] * B[noff.., 128]^T via smem + ldmatrix + mma.
// fp32 via 3-product bf16 split (Ah*Bh + Al*Bh + Ah*Bl), fp32 reg accum.
// L=0: A = x (fp32, split in staging), B=g_B0h/l, C=g_l0 (CS=256, 2 slabs).
// L=1: A = g_hh/g_hl, B=g_B1h/l, C=g_l1 (CS=64, NN=64).
// The h-columns (noff==0) also produce a_src/a_dst logits in the epilogue.
template <int L, int NN, int CS>
__global__ void __launch_bounds__(256) k_mma(
    const float* __restrict__ xsrc,
    const float* __restrict__ attS, const float* __restrict__ attD, int M)
{
    constexpr int WNN = (NN == 128) ? 4 : 2;   // warps along n
    constexpr int WMN = 8 / WNN;               // warps along m
    constexpr int WARP_M = 128 / WMN;          // 64 or 32
    constexpr int WARP_N = 32;                 // one head per warp
    constexpr int MI = WARP_M / 16;            // 4 or 2
    constexpr int NI = WARP_N / 8;             // 4
    constexpr int PB = 272;                    // pitch bytes (17*16B -> conflict-free)
    constexpr int SM_AHI = 0;
    constexpr int SM_ALO = 128 * PB;
    constexpr int SM_BHI = 2 * 128 * PB;
    constexpr int SM_BLO = SM_BHI + NN * PB;

    const __nv_bfloat16* __restrict__ Bh = (L == 0) ? g_B0h : g_B1h;
    const __nv_bfloat16* __restrict__ Bl = (L == 0) ? g_B0l : g_B1l;
    float* __restrict__ C = (L == 0) ? g_l0 : g_l1;

    extern __shared__ char smem[];
    uint32_t sb = smem_u32(smem);
    int tid = threadIdx.x, wid = tid >> 5, lane = tid & 31;
    int base = blockIdx.x * 128;
    int noff = blockIdx.y * NN;

    // ---- stage B slab (bf16 hi/lo)
    for (int idx = tid; idx < NN * 16; idx += 256) {
        int row = idx >> 4, q = idx & 15;
        *(uint4*)(smem + SM_BHI + row * PB + q * 16) = *(const uint4*)(Bh + (size_t)(noff + row) * 128 + q * 8);
        *(uint4*)(smem + SM_BLO + row * PB + q * 16) = *(const uint4*)(Bl + (size_t)(noff + row) * 128 + q * 8);
    }
    // ---- stage A
    if (L == 0) {
        // load fp32 x, split to bf16 hi/lo in registers (fused k_split)
        for (int idx = tid; idx < 128 * 32; idx += 256) {
            int row = idx >> 5, q = idx & 31;
            int gr = base + row;
            float4 v = make_float4(0.f, 0.f, 0.f, 0.f);
            if (gr < M) v = *(const float4*)(xsrc + (size_t)gr * 128 + q * 4);
            __nv_bfloat16 hx = __float2bfloat16_rn(v.x), hy = __float2bfloat16_rn(v.y);
            __nv_bfloat16 hz = __float2bfloat16_rn(v.z), hw = __float2bfloat16_rn(v.w);
            __nv_bfloat16 lx = __float2bfloat16_rn(v.x - __bfloat162float(hx));
            __nv_bfloat16 ly = __float2bfloat16_rn(v.y - __bfloat162float(hy));
            __nv_bfloat16 lz = __float2bfloat16_rn(v.z - __bfloat162float(hz));
            __nv_bfloat16 lw = __float2bfloat16_rn(v.w - __bfloat162float(hw));
            __nv_bfloat162 h01(hx, hy), h23(hz, hw), l01(lx, ly), l23(lz, lw);
            uint2 uh, ul;
            uh.x = *reinterpret_cast<uint32_t*>(&h01); uh.y = *reinterpret_cast<uint32_t*>(&h23);
            ul.x = *reinterpret_cast<uint32_t*>(&l01); ul.y = *reinterpret_cast<uint32_t*>(&l23);
            *(uint2*)(smem + SM_AHI + row * PB + q * 8) = uh;
            *(uint2*)(smem + SM_ALO + row * PB + q * 8) = ul;
        }
    } else {
        // bf16 hi/lo already materialized by k_agg0 (padded rows are zero)
        for (int idx = tid; idx < 128 * 16; idx += 256) {
            int row = idx >> 4, q = idx & 15;
            *(uint4*)(smem + SM_AHI + row * PB + q * 16) = *(const uint4*)(g_hh + (size_t)(base + row) * 128 + q * 8);
            *(uint4*)(smem + SM_ALO + row * PB + q * 16) = *(const uint4*)(g_hl + (size_t)(base + row) * 128 + q * 8);
        }
    }
    __syncthreads();

    int wm = (wid / WNN) * WARP_M;
    int wn = (wid % WNN) * WARP_N;          // smem-local col offset

    uint32_t a_off = (uint32_t)((wm + (lane & 15)) * PB + (lane >> 4) * 16);
    uint32_t b_off = (uint32_t)((wn + (lane & 7)) * PB + (((lane & 15) >> 3)) * 16);

    float acc[MI][NI][4];
#pragma unroll
    for (int mi = 0; mi < MI; mi++)
#pragma unroll
        for (int ni = 0; ni < NI; ni++)
#pragma unroll
            for (int r = 0; r < 4; r++) acc[mi][ni][r] = 0.f;

#pragma unroll
    for (int p = 0; p < 3; p++) {
        uint32_t abase = sb + ((p == 1) ? SM_ALO : SM_AHI) + a_off;
        uint32_t bbase = sb + ((p == 2) ? SM_BLO : SM_BHI) + b_off;
#pragma unroll
        for (int ks = 0; ks < 8; ks++) {
            uint32_t a[MI][4], b[NI][2];
#pragma unroll
            for (int mi = 0; mi < MI; mi++)
                ldsm_x4(a[mi], abase + mi * 16 * PB + ks * 32);
#pragma unroll
            for (int ni = 0; ni < NI; ni++)
                ldsm_x2(b[ni], bbase + ni * 8 * PB + ks * 32);
#pragma unroll
            for (int mi = 0; mi < MI; mi++)
#pragma unroll
                for (int ni = 0; ni < NI; ni++)
                    mma_bf16(acc[mi][ni], a[mi], b[ni]);
        }
    }

    // ---- C store: d0,d1 -> (row g, col tg*2..+1); d2,d3 -> row g+8
    int g = lane >> 2, tg = lane & 3;
#pragma unroll
    for (int mi = 0; mi < MI; mi++) {
        int r0 = base + wm + mi * 16 + g;
#pragma unroll
        for (int ni = 0; ni < NI; ni++) {
            int col = noff + wn + ni * 8 + tg * 2;
            *(float2*)(C + (size_t)r0 * CS + col)       = make_float2(acc[mi][ni][0], acc[mi][ni][1]);
            *(float2*)(C + (size_t)(r0 + 8) * CS + col) = make_float2(acc[mi][ni][2], acc[mi][ni][3]);
        }
    }

    // ---- fused attention logits (h-columns only: noff==0)
    if (noff == 0) {
        int head = wid % WNN;               // 32-col group = one head (L0), head0 (L1)
        if (L == 1 && head != 0) return;
        float s_w[NI * 2], d_w[NI * 2];
#pragma unroll
        for (int ni = 0; ni < NI; ni++) {
            int ci = ni * 8 + tg * 2;
            s_w[ni * 2]     = __ldg(attS + head * 32 + ci);
            s_w[ni * 2 + 1] = __ldg(attS + head * 32 + ci + 1);
            d_w[ni * 2]     = __ldg(attD + head * 32 + ci);
            d_w[ni * 2 + 1] = __ldg(attD + head * 32 + ci + 1);
        }
#pragma unroll
        for (int mi = 0; mi < MI; mi++) {
            float s0 = 0.f, d0 = 0.f, s1 = 0.f, d1 = 0.f;
#pragma unroll
            for (int ni = 0; ni < NI; ni++) {
                s0 = fmaf(acc[mi][ni][0], s_w[ni * 2], fmaf(acc[mi][ni][1], s_w[ni * 2 + 1], s0));
                d0 = fmaf(acc[mi][ni][0], d_w[ni * 2], fmaf(acc[mi][ni][1], d_w[ni * 2 + 1], d0));
                s1 = fmaf(acc[mi][ni][2], s_w[ni * 2], fmaf(acc[mi][ni][3], s_w[ni * 2 + 1], s1));
                d1 = fmaf(acc[mi][ni][2], d_w[ni * 2], fmaf(acc[mi][ni][3], d_w[ni * 2 + 1], d1));
            }
#pragma unroll
            for (int o = 1; o <= 2; o <<= 1) {
                s0 += __shfl_xor_sync(0xffffffffu, s0, o);
                d0 += __shfl_xor_sync(0xffffffffu, d0, o);
                s1 += __shfl_xor_sync(0xffffffffu, s1, o);
                d1 += __shfl_xor_sync(0xffffffffu, d1, o);
            }
            if (tg == 0) {
                int r0 = base + wm + mi * 16 + g;
                int r1 = r0 + 8;
                if (L == 0) {
                    if (r0 < M) { g_as0[r0 * 4 + head] = s0; g_ad0[r0 * 4 + head] = d0; }
                    if (r1 < M) { g_as0[r1 * 4 + head] = s1; g_ad0[r1 * 4 + head] = d1; }
                } else {
                    if (r0 < M) { g_as1[r0] = s0; g_ad1[r0] = d0; }
                    if (r1 < M) { g_as1[r1] = s1; g_ad1[r1] = d1; }
                }
            }
        }
    }
}

// ---------------- layer-0 aggregation: warp per dst node --------------------
// Single pass over edges: weights exp(leaky(e)) computed lane-parallel per
// 32-edge chunk into smem, denominator accumulated, gather uses LDS broadcast.
// (No max subtraction: softmax is shift-invariant and |e| << 88.)
__global__ void k_agg0(const float* __restrict__ bias0, const float* __restrict__ linb0, int n) {
    __shared__ float sw[8][32][4];
    int gw = (blockIdx.x * blockDim.x + threadIdx.x) >> 5;
    int warp = threadIdx.x >> 5;
    int lane = threadIdx.x & 31;
    if (gw >= n) return;
    int beg = g_rowptr[gw], end = g_rowptr[gw + 1];

    int   hsel = lane & 3;
    float4 ad4 = *(const float4*)(g_ad0 + gw * 4);
    float adh = (hsel == 0) ? ad4.x : (hsel == 1) ? ad4.y : (hsel == 2) ? ad4.z : ad4.w;

    float dn = 0.f;
    float acc0 = 0.f, acc1 = 0.f, acc2 = 0.f, acc3 = 0.f;

    for (int cbeg = beg; cbeg < end; cbeg += 32) {
        int cnt = min(32, end - cbeg);
        // weights: lane covers (edge = c*8 + lane>>2, head = lane&3)
#pragma unroll
        for (int c = 0; c < 4; c++) {
            int ei = c * 8 + (lane >> 2);
            float w = 0.f;
            if (ei < cnt) {
                int s = g_csr_src[cbeg + ei];
                float ev = g_as0[s * 4 + hsel] + adh;
                ev = ev > 0.f ? ev : 0.2f * ev;
                w = __expf(ev);
            }
            sw[warp][ei][hsel] = w;
            dn += w;
        }
        __syncwarp();
        // gather: per edge, LDS.128 broadcast of 4 head weights + 4 coalesced LDG
#pragma unroll 2
        for (int e2 = 0; e2 < cnt; e2++) {
            float4 w4 = *(const float4*)&sw[warp][e2][0];
            int s = g_csr_src[cbeg + e2];
            const float* row = g_l0 + (size_t)s * 256;
            acc0 = fmaf(w4.x, row[lane],      acc0);
            acc1 = fmaf(w4.y, row[32 + lane], acc1);
            acc2 = fmaf(w4.z, row[64 + lane], acc2);
            acc3 = fmaf(w4.w, row[96 + lane], acc3);
        }
        __syncwarp();
    }

    // reduce denominators (lanes with equal lane&3 share a head)
#pragma unroll
    for (int o = 4; o <= 16; o <<= 1) dn += __shfl_xor_sync(0xffffffffu, dn, o);
    float invh = 1.f / (dn + 1e-16f);
    float inv0 = __shfl_sync(0xffffffffu, invh, 0);
    float inv1 = __shfl_sync(0xffffffffu, invh, 1);
    float inv2 = __shfl_sync(0xffffffffu, invh, 2);
    float inv3 = __shfl_sync(0xffffffffu, invh, 3);

    const float* skip = g_l0 + (size_t)gw * 256 + 128;
    float o0 = acc0 * inv0 + bias0[lane]      + linb0[lane]      + skip[lane];
    float o1 = acc1 * inv1 + bias0[32 + lane] + linb0[32 + lane] + skip[32 + lane];
    float o2 = acc2 * inv2 + bias0[64 + lane] + linb0[64 + lane] + skip[64 + lane];
    float o3 = acc3 * inv3 + bias0[96 + lane] + linb0[96 + lane] + skip[96 + lane];
    o0 = o0 > 0.f ? o0 : (__expf(o0) - 1.f);
    o1 = o1 > 0.f ? o1 : (__expf(o1) - 1.f);
    o2 = o2 > 0.f ? o2 : (__expf(o2) - 1.f);
    o3 = o3 > 0.f ? o3 : (__expf(o3) - 1.f);

    size_t rb = (size_t)gw * 128;
    __nv_bfloat16 h;
    h = __float2bfloat16_rn(o0); g_hh[rb + lane]      = h; g_hl[rb + lane]      = __float2bfloat16_rn(o0 - __bfloat162float(h));
    h = __float2bfloat16_rn(o1); g_hh[rb + 32 + lane] = h; g_hl[rb + 32 + lane] = __float2bfloat16_rn(o1 - __bfloat162float(h));
    h = __float2bfloat16_rn(o2); g_hh[rb + 64 + lane] = h; g_hl[rb + 64 + lane] = __float2bfloat16_rn(o2 - __bfloat162float(h));
    h = __float2bfloat16_rn(o3); g_hh[rb + 96 + lane] = h; g_hl[rb + 96 + lane] = __float2bfloat16_rn(o3 - __bfloat162float(h));
}

// ---------------- layer-1 aggregation: warp per dst node --------------------
__global__ void k_agg1(const float* __restrict__ bias1, const float* __restrict__ linb1,
                       float* __restrict__ out, int n) {
    __shared__ float sw1[8][32];
    int gw = (blockIdx.x * blockDim.x + threadIdx.x) >> 5;
    int warp = threadIdx.x >> 5;
    int lane = threadIdx.x & 31;
    if (gw >= n) return;
    int beg = g_rowptr[gw], end = g_rowptr[gw + 1];
    float ad = g_ad1[gw];

    float dn = 0.f;
    float acc = 0.f;
    for (int cbeg = beg; cbeg < end; cbeg += 32) {
        int cnt = min(32, end - cbeg);
        int ei = cbeg + lane;
        float w = 0.f;
        if (lane < cnt) {
            float ev = g_as1[g_csr_src[ei]] + ad;
            ev = ev > 0.f ? ev : 0.2f * ev;
            w = __expf(ev);
        }
        sw1[warp][lane] = w;
        dn += w;
        __syncwarp();
#pragma unroll 2
        for (int e2 = 0; e2 < cnt; e2++) {
            int s = g_csr_src[cbeg + e2];
            acc = fmaf(sw1[warp][e2], g_l1[(size_t)s * 64 + lane], acc);
        }
        __syncwarp();
    }
#pragma unroll
    for (int o = 16; o; o >>= 1) dn += __shfl_xor_sync(0xffffffffu, dn, o);
    float inv = 1.f / (dn + 1e-16f);

    out[(size_t)gw * 32 + lane] =
        acc * inv + bias1[lane] + linb1[lane] + g_l1[(size_t)gw * 64 + 32 + lane];
}

// ---------------- launcher ---------------------------------------------------
extern "C" void kernel_launch(void* const* d_in, const int* in_sizes, int n_in,
                              void* d_out, int out_size) {
    const float* x   = (const float*)d_in[0];
    const int*   ei  = (const int*)  d_in[1];
    const float* W0  = (const float*)d_in[2];
    const float* as0 = (const float*)d_in[3];
    const float* ad0 = (const float*)d_in[4];
    const float* b0  = (const float*)d_in[5];
    const float* lW0 = (const float*)d_in[6];
    const float* lb0 = (const float*)d_in[7];
    const float* W1  = (const float*)d_in[8];
    const float* as1 = (const float*)d_in[9];
    const float* ad1 = (const float*)d_in[10];
    const float* b1  = (const float*)d_in[11];
    const float* lW1 = (const float*)d_in[12];
    const float* lb1 = (const float*)d_in[13];
    float* out = (float*)d_out;

    int n = in_sizes[0] / 128;
    int e = in_sizes[1] / 2;
    int etot = n + e;
    int nb = (n + SCAN_BS - 1) / SCAN_BS;
    int ntiles = (n + 127) / 128;

    const int smem0 = 2 * 128 * 272 + 2 * 128 * 272;  // 139264
    const int smem1 = 2 * 128 * 272 + 2 * 64 * 272;   // 104448
    cudaFuncSetAttribute(k_mma<0, 128, 256>, cudaFuncAttributeMaxDynamicSharedMemorySize, smem0);
    cudaFuncSetAttribute(k_mma<1, 64, 64>,   cudaFuncAttributeMaxDynamicSharedMemorySize, smem1);

    // setup (weight split + degree zero), CSR build
    k_setup<<<(n + 255) / 256, 256>>>(W0, lW0, W1, lW1, n);
    k_hist<<<(etot + 255) / 256, 256>>>(ei, e, etot);
    k_scan1<<<nb, SCAN_BS>>>(n);
    k_scan2<<<1, SCAN_BS>>>(nb);
    k_scan3<<<(n + 255) / 256, 256>>>(n);
    k_scatter<<<(etot + 255) / 256, 256>>>(ei, e, etot);

    // layer 0: HMMA GEMM (2 slabs; slab0 fuses a_src/a_dst + x split), agg
    k_mma<0, 128, 256><<<dim3(ntiles, 2), 256, smem0>>>(x, as0, ad0, n);
    k_agg0<<<(n + 7) / 8, 256>>>(b0, lb0, n);

    // layer 1: HMMA GEMM (fused logits), agg
    k_mma<1, 64, 64><<<dim3(ntiles, 1), 256, smem1>>>(x, as1, ad1, n);
    k_agg1<<<(n + 7) / 8, 256>>>(b1, lb1, out, n);
}

// round 10
// speedup vs baseline: 1.5108x; 1.1096x over previous
#include <cuda_runtime.h>
#include <cuda_bf16.h>
#include <cstdint>

// ---------------- problem-size constants (fixed by the reference) ----------
#define NNODES   50000
#define NPAD     50048                  // padded to multiple of 128
#define NEDGES   800000
#define ETOT     (NNODES + NEDGES)      // 850000 (edges + self loops)
#define SCAN_BS  512

// ---------------- device scratch (no allocations allowed) ------------------
// ONLY referenced from device code (host-side use of a __device__ symbol as a
// kernel arg silently reads the host shadow via ATS -> zero output).
__device__ float g_l0[(size_t)NPAD * 256];   // [x@W0^T | x@linW0^T]
__device__ float g_l1[(size_t)NPAD * 64];    // [h@W1^T | h@linW1^T]
__device__ __nv_bfloat16 g_hh[(size_t)NPAD * 128];
__device__ __nv_bfloat16 g_hl[(size_t)NPAD * 128];
__device__ float g_as0[NNODES * 4];
__device__ float g_ad0[NNODES * 4];
__device__ float g_as1[NNODES];
__device__ float g_ad1[NNODES];
__device__ int   g_deg[NNODES + 64];
__device__ int   g_rowtmp[NNODES + 64];
__device__ int   g_rowptr[NNODES + 64];
__device__ int   g_cursor[NNODES + 64];
__device__ int   g_csr_src[ETOT + 64];
__device__ int   g_bsum[SCAN_BS];
__device__ int   g_boff[SCAN_BS];
__device__ __nv_bfloat16 g_B0h[256 * 128];
__device__ __nv_bfloat16 g_B0l[256 * 128];
__device__ __nv_bfloat16 g_B1h[64 * 128];
__device__ __nv_bfloat16 g_B1l[64 * 128];

// ---------------- helpers ---------------------------------------------------
__device__ __forceinline__ uint32_t smem_u32(const void* p) {
    uint32_t a;
    asm("{ .reg .u64 t; cvta.to.shared.u64 t, %1; cvt.u32.u64 %0, t; }" : "=r"(a) : "l"(p));
    return a;
}
__device__ __forceinline__ void ldsm_x4(uint32_t* r, uint32_t addr) {
    asm volatile("ldmatrix.sync.aligned.m8n8.x4.shared.b16 {%0,%1,%2,%3}, [%4];"
                 : "=r"(r[0]), "=r"(r[1]), "=r"(r[2]), "=r"(r[3]) : "r"(addr));
}
__device__ __forceinline__ void ldsm_x2(uint32_t* r, uint32_t addr) {
    asm volatile("ldmatrix.sync.aligned.m8n8.x2.shared.b16 {%0,%1}, [%2];"
                 : "=r"(r[0]), "=r"(r[1]) : "r"(addr));
}
__device__ __forceinline__ void mma_bf16(float* d, const uint32_t* a, const uint32_t* b) {
    asm volatile(
        "mma.sync.aligned.m16n8k16.row.col.f32.bf16.bf16.f32 "
        "{%0,%1,%2,%3}, {%4,%5,%6,%7}, {%8,%9}, {%0,%1,%2,%3};"
        : "+f"(d[0]), "+f"(d[1]), "+f"(d[2]), "+f"(d[3])
        : "r"(a[0]), "r"(a[1]), "r"(a[2]), "r"(a[3]), "r"(b[0]), "r"(b[1]));
}

// ---------------- setup: weight split + degree zero -------------------------
__global__ void k_setup(const float* __restrict__ W0, const float* __restrict__ lW0,
                        const float* __restrict__ W1, const float* __restrict__ lW1, int n) {
    int i = blockIdx.x * blockDim.x + threadIdx.x;
    if (i < 128 * 128) {
        float v = W0[i];
        __nv_bfloat16 h = __float2bfloat16_rn(v);
        g_B0h[i] = h; g_B0l[i] = __float2bfloat16_rn(v - __bfloat162float(h));
        v = lW0[i];
        h = __float2bfloat16_rn(v);
        g_B0h[128 * 128 + i] = h; g_B0l[128 * 128 + i] = __float2bfloat16_rn(v - __bfloat162float(h));
    }
    if (i < 32 * 128) {
        float v = W1[i];
        __nv_bfloat16 h = __float2bfloat16_rn(v);
        g_B1h[i] = h; g_B1l[i] = __float2bfloat16_rn(v - __bfloat162float(h));
        v = lW1[i];
        h = __float2bfloat16_rn(v);
        g_B1h[32 * 128 + i] = h; g_B1l[32 * 128 + i] = __float2bfloat16_rn(v - __bfloat162float(h));
    }
    if (i < n) g_deg[i] = 0;
}

// ---------------- CSR build -------------------------------------------------
__global__ void k_hist(const int* __restrict__ ei, int e, int etot) {
    int k = blockIdx.x * blockDim.x + threadIdx.x;
    if (k >= etot) return;
    int dst = (k < e) ? ei[e + k] : (k - e);
    atomicAdd(&g_deg[dst], 1);
}
__global__ void k_scan1(int n) {
    __shared__ int sh[SCAN_BS];
    int t = threadIdx.x;
    int i = blockIdx.x * SCAN_BS + t;
    int v = (i < n) ? g_deg[i] : 0;
    sh[t] = v;
    __syncthreads();
    for (int o = 1; o < SCAN_BS; o <<= 1) {
        int x = (t >= o) ? sh[t - o] : 0;
        __syncthreads();
        sh[t] += x;
        __syncthreads();
    }
    if (i < n) g_rowtmp[i] = sh[t];
    if (t == SCAN_BS - 1) g_bsum[blockIdx.x] = sh[t];
}
__global__ void k_scan2(int nb) {
    __shared__ int sh[SCAN_BS];
    int t = threadIdx.x;
    int v = (t < nb) ? g_bsum[t] : 0;
    sh[t] = v;
    __syncthreads();
    for (int o = 1; o < SCAN_BS; o <<= 1) {
        int x = (t >= o) ? sh[t - o] : 0;
        __syncthreads();
        sh[t] += x;
        __syncthreads();
    }
    if (t < nb) g_boff[t] = sh[t] - v;
}
__global__ void k_scan3(int n) {
    int i = blockIdx.x * blockDim.x + threadIdx.x;
    if (i >= n) return;
    int incl = g_rowtmp[i] + g_boff[i >> 9];
    g_rowptr[i + 1] = incl;
    g_cursor[i] = incl - g_deg[i];
    if (i == 0) g_rowptr[0] = 0;
}
__global__ void k_scatter(const int* __restrict__ ei, int e, int etot) {
    int k = blockIdx.x * blockDim.x + threadIdx.x;
    if (k >= etot) return;
    int src, dst;
    if (k < e) { src = ei[k]; dst = ei[e + k]; }
    else       { src = dst = k - e; }
    int pos = atomicAdd(&g_cursor[dst], 1);
    g_csr_src[pos] = src;
}

// ---------------- HMMA GEMM + fused attention logits -------------------------
// Single launch per layer. A staged once; B processed in NSLAB slabs of NN
// columns inside the kernel (acc registers reused -> round-8 register profile).
// fp32 via 3-product bf16 split (Ah*Bh + Al*Bh + Ah*Bl), fp32 reg accum.
// L=0: A = x (fp32, split in staging), B=g_B0h/l, C=g_l0, 2 slabs of 128.
// L=1: A = g_hh/g_hl, B=g_B1h/l, C=g_l1, 1 slab of 64.
// Slab 0 covers the h-columns: fused a_src/a_dst logits in its epilogue.
template <int L>
__global__ void __launch_bounds__(256) k_mma(
    const float* __restrict__ xsrc,
    const float* __restrict__ attS, const float* __restrict__ attD, int M)
{
    constexpr int NSLAB = (L == 0) ? 2 : 1;
    constexpr int NN  = (L == 0) ? 128 : 64;   // cols per slab
    constexpr int CS  = (L == 0) ? 256 : 64;   // C row stride
    constexpr int WNN = (NN == 128) ? 4 : 2;   // warps along n
    constexpr int WMN = 8 / WNN;               // warps along m
    constexpr int WARP_M = 128 / WMN;          // 64 or 32
    constexpr int MI = WARP_M / 16;            // 4 or 2
    constexpr int NI = 4;                      // WARP_N = 32 (one head)
    constexpr int PB = 272;                    // pitch bytes (17*16B -> conflict-free)
    constexpr int SM_AHI = 0;
    constexpr int SM_ALO = 128 * PB;
    constexpr int SM_BHI = 2 * 128 * PB;
    constexpr int SM_BLO = SM_BHI + NN * PB;

    const __nv_bfloat16* __restrict__ Bh = (L == 0) ? g_B0h : g_B1h;
    const __nv_bfloat16* __restrict__ Bl = (L == 0) ? g_B0l : g_B1l;
    float* __restrict__ C = (L == 0) ? g_l0 : g_l1;

    extern __shared__ char smem[];
    uint32_t sb = smem_u32(smem);
    int tid = threadIdx.x, wid = tid >> 5, lane = tid & 31;
    int base = blockIdx.x * 128;

    // ---- stage A once
    if (L == 0) {
        // load fp32 x, split to bf16 hi/lo in registers (fused split)
        for (int idx = tid; idx < 128 * 32; idx += 256) {
            int row = idx >> 5, q = idx & 31;
            int gr = base + row;
            float4 v = make_float4(0.f, 0.f, 0.f, 0.f);
            if (gr < M) v = *(const float4*)(xsrc + (size_t)gr * 128 + q * 4);
            __nv_bfloat16 hx = __float2bfloat16_rn(v.x), hy = __float2bfloat16_rn(v.y);
            __nv_bfloat16 hz = __float2bfloat16_rn(v.z), hw = __float2bfloat16_rn(v.w);
            __nv_bfloat16 lx = __float2bfloat16_rn(v.x - __bfloat162float(hx));
            __nv_bfloat16 ly = __float2bfloat16_rn(v.y - __bfloat162float(hy));
            __nv_bfloat16 lz = __float2bfloat16_rn(v.z - __bfloat162float(hz));
            __nv_bfloat16 lw = __float2bfloat16_rn(v.w - __bfloat162float(hw));
            __nv_bfloat162 h01(hx, hy), h23(hz, hw), l01(lx, ly), l23(lz, lw);
            uint2 uh, ul;
            uh.x = *reinterpret_cast<uint32_t*>(&h01); uh.y = *reinterpret_cast<uint32_t*>(&h23);
            ul.x = *reinterpret_cast<uint32_t*>(&l01); ul.y = *reinterpret_cast<uint32_t*>(&l23);
            *(uint2*)(smem + SM_AHI + row * PB + q * 8) = uh;
            *(uint2*)(smem + SM_ALO + row * PB + q * 8) = ul;
        }
    } else {
        // bf16 hi/lo already materialized by k_agg0 (padded rows are zero)
        for (int idx = tid; idx < 128 * 16; idx += 256) {
            int row = idx >> 4, q = idx & 15;
            *(uint4*)(smem + SM_AHI + row * PB + q * 16) = *(const uint4*)(g_hh + (size_t)(base + row) * 128 + q * 8);
            *(uint4*)(smem + SM_ALO + row * PB + q * 16) = *(const uint4*)(g_hl + (size_t)(base + row) * 128 + q * 8);
        }
    }

    int wm = (wid / WNN) * WARP_M;
    int wn = (wid % WNN) * 32;

    uint32_t a_off = (uint32_t)((wm + (lane & 15)) * PB + (lane >> 4) * 16);
    uint32_t b_off = (uint32_t)((wn + (lane & 7)) * PB + (((lane & 15) >> 3)) * 16);

#pragma unroll
    for (int slab = 0; slab < NSLAB; slab++) {
        int noff = slab * NN;
        // ---- stage B slab (bf16 hi/lo)
        for (int idx = tid; idx < NN * 16; idx += 256) {
            int row = idx >> 4, q = idx & 15;
            *(uint4*)(smem + SM_BHI + row * PB + q * 16) = *(const uint4*)(Bh + (size_t)(noff + row) * 128 + q * 8);
            *(uint4*)(smem + SM_BLO + row * PB + q * 16) = *(const uint4*)(Bl + (size_t)(noff + row) * 128 + q * 8);
        }
        __syncthreads();

        float acc[MI][NI][4];
#pragma unroll
        for (int mi = 0; mi < MI; mi++)
#pragma unroll
            for (int ni = 0; ni < NI; ni++)
#pragma unroll
                for (int r = 0; r < 4; r++) acc[mi][ni][r] = 0.f;

#pragma unroll
        for (int p = 0; p < 3; p++) {
            uint32_t abase = sb + ((p == 1) ? SM_ALO : SM_AHI) + a_off;
            uint32_t bbase = sb + ((p == 2) ? SM_BLO : SM_BHI) + b_off;
#pragma unroll
            for (int ks = 0; ks < 8; ks++) {
                uint32_t a[MI][4], b[NI][2];
#pragma unroll
                for (int mi = 0; mi < MI; mi++)
                    ldsm_x4(a[mi], abase + mi * 16 * PB + ks * 32);
#pragma unroll
                for (int ni = 0; ni < NI; ni++)
                    ldsm_x2(b[ni], bbase + ni * 8 * PB + ks * 32);
#pragma unroll
                for (int mi = 0; mi < MI; mi++)
#pragma unroll
                    for (int ni = 0; ni < NI; ni++)
                        mma_bf16(acc[mi][ni], a[mi], b[ni]);
            }
        }

        // ---- C store: d0,d1 -> (row g, col tg*2..+1); d2,d3 -> row g+8
        int g = lane >> 2, tg = lane & 3;
#pragma unroll
        for (int mi = 0; mi < MI; mi++) {
            int r0 = base + wm + mi * 16 + g;
#pragma unroll
            for (int ni = 0; ni < NI; ni++) {
                int col = noff + wn + ni * 8 + tg * 2;
                *(float2*)(C + (size_t)r0 * CS + col)       = make_float2(acc[mi][ni][0], acc[mi][ni][1]);
                *(float2*)(C + (size_t)(r0 + 8) * CS + col) = make_float2(acc[mi][ni][2], acc[mi][ni][3]);
            }
        }

        // ---- fused attention logits (h-columns: slab 0 only)
        int head = wid % WNN;
        if (slab == 0 && !(L == 1 && head != 0)) {
            float s_w[NI * 2], d_w[NI * 2];
#pragma unroll
            for (int ni = 0; ni < NI; ni++) {
                int ci = ni * 8 + tg * 2;
                s_w[ni * 2]     = __ldg(attS + head * 32 + ci);
                s_w[ni * 2 + 1] = __ldg(attS + head * 32 + ci + 1);
                d_w[ni * 2]     = __ldg(attD + head * 32 + ci);
                d_w[ni * 2 + 1] = __ldg(attD + head * 32 + ci + 1);
            }
#pragma unroll
            for (int mi = 0; mi < MI; mi++) {
                float s0 = 0.f, d0 = 0.f, s1 = 0.f, d1 = 0.f;
#pragma unroll
                for (int ni = 0; ni < NI; ni++) {
                    s0 = fmaf(acc[mi][ni][0], s_w[ni * 2], fmaf(acc[mi][ni][1], s_w[ni * 2 + 1], s0));
                    d0 = fmaf(acc[mi][ni][0], d_w[ni * 2], fmaf(acc[mi][ni][1], d_w[ni * 2 + 1], d0));
                    s1 = fmaf(acc[mi][ni][2], s_w[ni * 2], fmaf(acc[mi][ni][3], s_w[ni * 2 + 1], s1));
                    d1 = fmaf(acc[mi][ni][2], d_w[ni * 2], fmaf(acc[mi][ni][3], d_w[ni * 2 + 1], d1));
                }
#pragma unroll
                for (int o = 1; o <= 2; o <<= 1) {
                    s0 += __shfl_xor_sync(0xffffffffu, s0, o);
                    d0 += __shfl_xor_sync(0xffffffffu, d0, o);
                    s1 += __shfl_xor_sync(0xffffffffu, s1, o);
                    d1 += __shfl_xor_sync(0xffffffffu, d1, o);
                }
                if (tg == 0) {
                    int r0 = base + wm + mi * 16 + g;
                    int r1 = r0 + 8;
                    if (L == 0) {
                        if (r0 < M) { g_as0[r0 * 4 + head] = s0; g_ad0[r0 * 4 + head] = d0; }
                        if (r1 < M) { g_as0[r1 * 4 + head] = s1; g_ad0[r1 * 4 + head] = d1; }
                    } else {
                        if (r0 < M) { g_as1[r0] = s0; g_ad1[r0] = d0; }
                        if (r1 < M) { g_as1[r1] = s1; g_ad1[r1] = d1; }
                    }
                }
            }
        }
        if (slab + 1 < NSLAB) __syncthreads();   // protect B restage
    }
}

// ---------------- layer-0 aggregation: warp per dst node --------------------
// Single pass over edges: weights exp(leaky(e)) computed lane-parallel per
// 32-edge chunk into smem (with src indices), denominator accumulated; gather
// uses LDS broadcast. (No max subtraction: softmax shift-invariant, |e|<<88.)
__global__ void k_agg0(const float* __restrict__ bias0, const float* __restrict__ linb0, int n) {
    __shared__ float sw[8][32][4];
    __shared__ int   ss[8][32];
    int gw = (blockIdx.x * blockDim.x + threadIdx.x) >> 5;
    int warp = threadIdx.x >> 5;
    int lane = threadIdx.x & 31;
    if (gw >= n) return;
    int beg = g_rowptr[gw], end = g_rowptr[gw + 1];

    int   hsel = lane & 3;
    float4 ad4 = *(const float4*)(g_ad0 + gw * 4);
    float adh = (hsel == 0) ? ad4.x : (hsel == 1) ? ad4.y : (hsel == 2) ? ad4.z : ad4.w;

    float dn = 0.f;
    float acc0 = 0.f, acc1 = 0.f, acc2 = 0.f, acc3 = 0.f;

    for (int cbeg = beg; cbeg < end; cbeg += 32) {
        int cnt = min(32, end - cbeg);
#pragma unroll
        for (int c = 0; c < 4; c++) {
            int ei = c * 8 + (lane >> 2);
            float w = 0.f;
            if (ei < cnt) {
                int s = g_csr_src[cbeg + ei];
                if (hsel == 0) ss[warp][ei] = s;
                float ev = g_as0[s * 4 + hsel] + adh;
                ev = ev > 0.f ? ev : 0.2f * ev;
                w = __expf(ev);
            }
            sw[warp][ei][hsel] = w;
            dn += w;
        }
        __syncwarp();
#pragma unroll 2
        for (int e2 = 0; e2 < cnt; e2++) {
            float4 w4 = *(const float4*)&sw[warp][e2][0];
            int s = ss[warp][e2];
            const float* row = g_l0 + (size_t)s * 256;
            acc0 = fmaf(w4.x, row[lane],      acc0);
            acc1 = fmaf(w4.y, row[32 + lane], acc1);
            acc2 = fmaf(w4.z, row[64 + lane], acc2);
            acc3 = fmaf(w4.w, row[96 + lane], acc3);
        }
        __syncwarp();
    }

#pragma unroll
    for (int o = 4; o <= 16; o <<= 1) dn += __shfl_xor_sync(0xffffffffu, dn, o);
    float invh = 1.f / (dn + 1e-16f);
    float inv0 = __shfl_sync(0xffffffffu, invh, 0);
    float inv1 = __shfl_sync(0xffffffffu, invh, 1);
    float inv2 = __shfl_sync(0xffffffffu, invh, 2);
    float inv3 = __shfl_sync(0xffffffffu, invh, 3);

    const float* skip = g_l0 + (size_t)gw * 256 + 128;
    float o0 = acc0 * inv0 + bias0[lane]      + linb0[lane]      + skip[lane];
    float o1 = acc1 * inv1 + bias0[32 + lane] + linb0[32 + lane] + skip[32 + lane];
    float o2 = acc2 * inv2 + bias0[64 + lane] + linb0[64 + lane] + skip[64 + lane];
    float o3 = acc3 * inv3 + bias0[96 + lane] + linb0[96 + lane] + skip[96 + lane];
    o0 = o0 > 0.f ? o0 : (__expf(o0) - 1.f);
    o1 = o1 > 0.f ? o1 : (__expf(o1) - 1.f);
    o2 = o2 > 0.f ? o2 : (__expf(o2) - 1.f);
    o3 = o3 > 0.f ? o3 : (__expf(o3) - 1.f);

    size_t rb = (size_t)gw * 128;
    __nv_bfloat16 h;
    h = __float2bfloat16_rn(o0); g_hh[rb + lane]      = h; g_hl[rb + lane]      = __float2bfloat16_rn(o0 - __bfloat162float(h));
    h = __float2bfloat16_rn(o1); g_hh[rb + 32 + lane] = h; g_hl[rb + 32 + lane] = __float2bfloat16_rn(o1 - __bfloat162float(h));
    h = __float2bfloat16_rn(o2); g_hh[rb + 64 + lane] = h; g_hl[rb + 64 + lane] = __float2bfloat16_rn(o2 - __bfloat162float(h));
    h = __float2bfloat16_rn(o3); g_hh[rb + 96 + lane] = h; g_hl[rb + 96 + lane] = __float2bfloat16_rn(o3 - __bfloat162float(h));
}

// ---------------- layer-1 aggregation: warp per dst node --------------------
__global__ void k_agg1(const float* __restrict__ bias1, const float* __restrict__ linb1,
                       float* __restrict__ out, int n) {
    __shared__ float sw1[8][32];
    __shared__ int   ss1[8][32];
    int gw = (blockIdx.x * blockDim.x + threadIdx.x) >> 5;
    int warp = threadIdx.x >> 5;
    int lane = threadIdx.x & 31;
    if (gw >= n) return;
    int beg = g_rowptr[gw], end = g_rowptr[gw + 1];
    float ad = g_ad1[gw];

    float dn = 0.f;
    float acc = 0.f;
    for (int cbeg = beg; cbeg < end; cbeg += 32) {
        int cnt = min(32, end - cbeg);
        float w = 0.f;
        if (lane < cnt) {
            int s = g_csr_src[cbeg + lane];
            ss1[warp][lane] = s;
            float ev = g_as1[s] + ad;
            ev = ev > 0.f ? ev : 0.2f * ev;
            w = __expf(ev);
        }
        sw1[warp][lane] = w;
        dn += w;
        __syncwarp();
#pragma unroll 2
        for (int e2 = 0; e2 < cnt; e2++) {
            int s = ss1[warp][e2];
            acc = fmaf(sw1[warp][e2], g_l1[(size_t)s * 64 + lane], acc);
        }
        __syncwarp();
    }
#pragma unroll
    for (int o = 16; o; o >>= 1) dn += __shfl_xor_sync(0xffffffffu, dn, o);
    float inv = 1.f / (dn + 1e-16f);

    out[(size_t)gw * 32 + lane] =
        acc * inv + bias1[lane] + linb1[lane] + g_l1[(size_t)gw * 64 + 32 + lane];
}

// ---------------- launcher ---------------------------------------------------
extern "C" void kernel_launch(void* const* d_in, const int* in_sizes, int n_in,
                              void* d_out, int out_size) {
    const float* x   = (const float*)d_in[0];
    const int*   ei  = (const int*)  d_in[1];
    const float* W0  = (const float*)d_in[2];
    const float* as0 = (const float*)d_in[3];
    const float* ad0 = (const float*)d_in[4];
    const float* b0  = (const float*)d_in[5];
    const float* lW0 = (const float*)d_in[6];
    const float* lb0 = (const float*)d_in[7];
    const float* W1  = (const float*)d_in[8];
    const float* as1 = (const float*)d_in[9];
    const float* ad1 = (const float*)d_in[10];
    const float* b1  = (const float*)d_in[11];
    const float* lW1 = (const float*)d_in[12];
    const float* lb1 = (const float*)d_in[13];
    float* out = (float*)d_out;

    int n = in_sizes[0] / 128;
    int e = in_sizes[1] / 2;
    int etot = n + e;
    int nb = (n + SCAN_BS - 1) / SCAN_BS;
    int ntiles = (n + 127) / 128;

    const int smem0 = 2 * 128 * 272 + 2 * 128 * 272;  // 139264
    const int smem1 = 2 * 128 * 272 + 2 * 64 * 272;   // 104448
    cudaFuncSetAttribute(k_mma<0>, cudaFuncAttributeMaxDynamicSharedMemorySize, smem0);
    cudaFuncSetAttribute(k_mma<1>, cudaFuncAttributeMaxDynamicSharedMemorySize, smem1);

    // setup (weight split + degree zero), CSR build
    k_setup<<<(n + 255) / 256, 256>>>(W0, lW0, W1, lW1, n);
    k_hist<<<(etot + 255) / 256, 256>>>(ei, e, etot);
    k_scan1<<<nb, SCAN_BS>>>(n);
    k_scan2<<<1, SCAN_BS>>>(nb);
    k_scan3<<<(n + 255) / 256, 256>>>(n);
    k_scatter<<<(etot + 255) / 256, 256>>>(ei, e, etot);

    // layer 0: single-launch HMMA GEMM (2 internal slabs, fused logits), agg
    k_mma<0><<<ntiles, 256, smem0>>>(x, as0, ad0, n);
    k_agg0<<<(n + 7) / 8, 256>>>(b0, lb0, n);

    // layer 1: HMMA GEMM (fused logits), agg
    k_mma<1><<<ntiles, 256, smem1>>>(x, as1, ad1, n);
    k_agg1<<<(n + 7) / 8, 256>>>(b1, lb1, out, n);
}

// round 11
// speedup vs baseline: 1.6455x; 1.0891x over previous
#include <cuda_runtime.h>
#include <cuda_bf16.h>
#include <cstdint>

// ---------------- problem-size constants (fixed by the reference) ----------
#define NNODES   50000
#define NPAD     50048                  // padded to multiple of 128
#define NEDGES   800000
#define ETOT     (NNODES + NEDGES)      // 850000 (edges + self loops)
#define SCAN_BS  512

// ---------------- device scratch (no allocations allowed) ------------------
// ONLY referenced from device code (host-side use of a __device__ symbol as a
// kernel arg silently reads the host shadow via ATS -> zero output).
__device__ float g_l0[(size_t)NPAD * 256];   // [x@W0^T | x@linW0^T]
__device__ float g_l1[(size_t)NPAD * 64];    // [h@W1^T | h@linW1^T]
__device__ __nv_bfloat16 g_hh[(size_t)NPAD * 128];
__device__ __nv_bfloat16 g_hl[(size_t)NPAD * 128];
__device__ float g_as0[NNODES * 4];
__device__ float g_ad0[NNODES * 4];
__device__ float g_as1[NNODES];
__device__ float g_ad1[NNODES];
__device__ int   g_deg[NNODES + 64];
__device__ int   g_rowtmp[NNODES + 64];
__device__ int   g_rowptr[NNODES + 64];
__device__ int   g_cursor[NNODES + 64];
__device__ int   g_csr_src[ETOT + 64];
__device__ int   g_bsum[SCAN_BS];
__device__ __nv_bfloat16 g_B0h[256 * 128];
__device__ __nv_bfloat16 g_B0l[256 * 128];
__device__ __nv_bfloat16 g_B1h[64 * 128];
__device__ __nv_bfloat16 g_B1l[64 * 128];

// ---------------- helpers ---------------------------------------------------
__device__ __forceinline__ uint32_t smem_u32(const void* p) {
    uint32_t a;
    asm("{ .reg .u64 t; cvta.to.shared.u64 t, %1; cvt.u32.u64 %0, t; }" : "=r"(a) : "l"(p));
    return a;
}
__device__ __forceinline__ void ldsm_x4(uint32_t* r, uint32_t addr) {
    asm volatile("ldmatrix.sync.aligned.m8n8.x4.shared.b16 {%0,%1,%2,%3}, [%4];"
                 : "=r"(r[0]), "=r"(r[1]), "=r"(r[2]), "=r"(r[3]) : "r"(addr));
}
__device__ __forceinline__ void ldsm_x2(uint32_t* r, uint32_t addr) {
    asm volatile("ldmatrix.sync.aligned.m8n8.x2.shared.b16 {%0,%1}, [%2];"
                 : "=r"(r[0]), "=r"(r[1]) : "r"(addr));
}
__device__ __forceinline__ void mma_bf16(float* d, const uint32_t* a, const uint32_t* b) {
    asm volatile(
        "mma.sync.aligned.m16n8k16.row.col.f32.bf16.bf16.f32 "
        "{%0,%1,%2,%3}, {%4,%5,%6,%7}, {%8,%9}, {%0,%1,%2,%3};"
        : "+f"(d[0]), "+f"(d[1]), "+f"(d[2]), "+f"(d[3])
        : "r"(a[0]), "r"(a[1]), "r"(a[2]), "r"(a[3]), "r"(b[0]), "r"(b[1]));
}

// ---------------- setup: weight split (default stream, feeds GEMM0) ---------
__global__ void k_setupW(const float* __restrict__ W0, const float* __restrict__ lW0,
                         const float* __restrict__ W1, const float* __restrict__ lW1) {
    int i = blockIdx.x * blockDim.x + threadIdx.x;
    if (i < 128 * 128) {
        float v = W0[i];
        __nv_bfloat16 h = __float2bfloat16_rn(v);
        g_B0h[i] = h; g_B0l[i] = __float2bfloat16_rn(v - __bfloat162float(h));
        v = lW0[i];
        h = __float2bfloat16_rn(v);
        g_B0h[128 * 128 + i] = h; g_B0l[128 * 128 + i] = __float2bfloat16_rn(v - __bfloat162float(h));
    }
    if (i < 32 * 128) {
        float v = W1[i];
        __nv_bfloat16 h = __float2bfloat16_rn(v);
        g_B1h[i] = h; g_B1l[i] = __float2bfloat16_rn(v - __bfloat162float(h));
        v = lW1[i];
        h = __float2bfloat16_rn(v);
        g_B1h[32 * 128 + i] = h; g_B1l[32 * 128 + i] = __float2bfloat16_rn(v - __bfloat162float(h));
    }
}

// ---------------- CSR build (stream s2) --------------------------------------
__global__ void k_zero_deg(int n) {
    int i = blockIdx.x * blockDim.x + threadIdx.x;
    if (i < n) g_deg[i] = 0;
}
__global__ void k_hist(const int* __restrict__ ei, int e, int etot) {
    int k = blockIdx.x * blockDim.x + threadIdx.x;
    if (k >= etot) return;
    int dst = (k < e) ? ei[e + k] : (k - e);
    atomicAdd(&g_deg[dst], 1);
}
__global__ void k_scan1(int n) {
    __shared__ int sh[SCAN_BS];
    int t = threadIdx.x;
    int i = blockIdx.x * SCAN_BS + t;
    int v = (i < n) ? g_deg[i] : 0;
    sh[t] = v;
    __syncthreads();
    for (int o = 1; o < SCAN_BS; o <<= 1) {
        int x = (t >= o) ? sh[t - o] : 0;
        __syncthreads();
        sh[t] += x;
        __syncthreads();
    }
    if (i < n) g_rowtmp[i] = sh[t];
    if (t == SCAN_BS - 1) g_bsum[blockIdx.x] = sh[t];
}
// merged scan2+scan3: block b (256 thr) lies fully in bsum region b>>1, so it
// block-reduces g_bsum[0..b>>1) and applies the exclusive region offset.
__global__ void k_scan23(int n) {
    __shared__ int red[256];
    int t = threadIdx.x, b = blockIdx.x;
    int region = b >> 1;                    // 512-wide regions, 256-wide blocks
    red[t] = (t < region) ? g_bsum[t] : 0;  // region <= 98 < 256
    __syncthreads();
    for (int o = 128; o; o >>= 1) {
        if (t < o) red[t] += red[t + o];
        __syncthreads();
    }
    int pre = red[0];
    int i = b * 256 + t;
    if (i < n) {
        int incl = g_rowtmp[i] + pre;
        g_rowptr[i + 1] = incl;
        g_cursor[i] = incl - g_deg[i];
        if (i == 0) g_rowptr[0] = 0;
    }
}
__global__ void k_scatter(const int* __restrict__ ei, int e, int etot) {
    int k = blockIdx.x * blockDim.x + threadIdx.x;
    if (k >= etot) return;
    int src, dst;
    if (k < e) { src = ei[k]; dst = ei[e + k]; }
    else       { src = dst = k - e; }
    int pos = atomicAdd(&g_cursor[dst], 1);
    g_csr_src[pos] = src;
}

// ---------------- HMMA GEMM + fused attention logits -------------------------
// Single launch per layer. A staged once; B processed in NSLAB slabs of NN
// columns inside the kernel (acc registers reused).
// fp32 via 3-product bf16 split (Ah*Bh + Al*Bh + Ah*Bl), fp32 reg accum.
// L=0: A = x (fp32, split in staging), B=g_B0h/l, C=g_l0, 2 slabs of 128.
// L=1: A = g_hh/g_hl, B=g_B1h/l, C=g_l1, 1 slab of 64.
// Slab 0 covers the h-columns: fused a_src/a_dst logits in its epilogue.
template <int L>
__global__ void __launch_bounds__(256) k_mma(
    const float* __restrict__ xsrc,
    const float* __restrict__ attS, const float* __restrict__ attD, int M)
{
    constexpr int NSLAB = (L == 0) ? 2 : 1;
    constexpr int NN  = (L == 0) ? 128 : 64;   // cols per slab
    constexpr int CS  = (L == 0) ? 256 : 64;   // C row stride
    constexpr int WNN = (NN == 128) ? 4 : 2;   // warps along n
    constexpr int WMN = 8 / WNN;               // warps along m
    constexpr int WARP_M = 128 / WMN;          // 64 or 32
    constexpr int MI = WARP_M / 16;            // 4 or 2
    constexpr int NI = 4;                      // WARP_N = 32 (one head)
    constexpr int PB = 272;                    // pitch bytes (17*16B -> conflict-free)
    constexpr int SM_AHI = 0;
    constexpr int SM_ALO = 128 * PB;
    constexpr int SM_BHI = 2 * 128 * PB;
    constexpr int SM_BLO = SM_BHI + NN * PB;

    const __nv_bfloat16* __restrict__ Bh = (L == 0) ? g_B0h : g_B1h;
    const __nv_bfloat16* __restrict__ Bl = (L == 0) ? g_B0l : g_B1l;
    float* __restrict__ C = (L == 0) ? g_l0 : g_l1;

    extern __shared__ char smem[];
    uint32_t sb = smem_u32(smem);
    int tid = threadIdx.x, wid = tid >> 5, lane = tid & 31;
    int base = blockIdx.x * 128;

    // ---- stage A once
    if (L == 0) {
        // load fp32 x, split to bf16 hi/lo in registers (fused split)
        for (int idx = tid; idx < 128 * 32; idx += 256) {
            int row = idx >> 5, q = idx & 31;
            int gr = base + row;
            float4 v = make_float4(0.f, 0.f, 0.f, 0.f);
            if (gr < M) v = *(const float4*)(xsrc + (size_t)gr * 128 + q * 4);
            __nv_bfloat16 hx = __float2bfloat16_rn(v.x), hy = __float2bfloat16_rn(v.y);
            __nv_bfloat16 hz = __float2bfloat16_rn(v.z), hw = __float2bfloat16_rn(v.w);
            __nv_bfloat16 lx = __float2bfloat16_rn(v.x - __bfloat162float(hx));
            __nv_bfloat16 ly = __float2bfloat16_rn(v.y - __bfloat162float(hy));
            __nv_bfloat16 lz = __float2bfloat16_rn(v.z - __bfloat162float(hz));
            __nv_bfloat16 lw = __float2bfloat16_rn(v.w - __bfloat162float(hw));
            __nv_bfloat162 h01(hx, hy), h23(hz, hw), l01(lx, ly), l23(lz, lw);
            uint2 uh, ul;
            uh.x = *reinterpret_cast<uint32_t*>(&h01); uh.y = *reinterpret_cast<uint32_t*>(&h23);
            ul.x = *reinterpret_cast<uint32_t*>(&l01); ul.y = *reinterpret_cast<uint32_t*>(&l23);
            *(uint2*)(smem + SM_AHI + row * PB + q * 8) = uh;
            *(uint2*)(smem + SM_ALO + row * PB + q * 8) = ul;
        }
    } else {
        // bf16 hi/lo already materialized by k_agg0 (padded rows are zero)
        for (int idx = tid; idx < 128 * 16; idx += 256) {
            int row = idx >> 4, q = idx & 15;
            *(uint4*)(smem + SM_AHI + row * PB + q * 16) = *(const uint4*)(g_hh + (size_t)(base + row) * 128 + q * 8);
            *(uint4*)(smem + SM_ALO + row * PB + q * 16) = *(const uint4*)(g_hl + (size_t)(base + row) * 128 + q * 8);
        }
    }

    int wm = (wid / WNN) * WARP_M;
    int wn = (wid % WNN) * 32;

    uint32_t a_off = (uint32_t)((wm + (lane & 15)) * PB + (lane >> 4) * 16);
    uint32_t b_off = (uint32_t)((wn + (lane & 7)) * PB + (((lane & 15) >> 3)) * 16);

#pragma unroll
    for (int slab = 0; slab < NSLAB; slab++) {
        int noff = slab * NN;
        // ---- stage B slab (bf16 hi/lo)
        for (int idx = tid; idx < NN * 16; idx += 256) {
            int row = idx >> 4, q = idx & 15;
            *(uint4*)(smem + SM_BHI + row * PB + q * 16) = *(const uint4*)(Bh + (size_t)(noff + row) * 128 + q * 8);
            *(uint4*)(smem + SM_BLO + row * PB + q * 16) = *(const uint4*)(Bl + (size_t)(noff + row) * 128 + q * 8);
        }
        __syncthreads();

        float acc[MI][NI][4];
#pragma unroll
        for (int mi = 0; mi < MI; mi++)
#pragma unroll
            for (int ni = 0; ni < NI; ni++)
#pragma unroll
                for (int r = 0; r < 4; r++) acc[mi][ni][r] = 0.f;

#pragma unroll
        for (int p = 0; p < 3; p++) {
            uint32_t abase = sb + ((p == 1) ? SM_ALO : SM_AHI) + a_off;
            uint32_t bbase = sb + ((p == 2) ? SM_BLO : SM_BHI) + b_off;
#pragma unroll
            for (int ks = 0; ks < 8; ks++) {
                uint32_t a[MI][4], b[NI][2];
#pragma unroll
                for (int mi = 0; mi < MI; mi++)
                    ldsm_x4(a[mi], abase + mi * 16 * PB + ks * 32);
#pragma unroll
                for (int ni = 0; ni < NI; ni++)
                    ldsm_x2(b[ni], bbase + ni * 8 * PB + ks * 32);
#pragma unroll
                for (int mi = 0; mi < MI; mi++)
#pragma unroll
                    for (int ni = 0; ni < NI; ni++)
                        mma_bf16(acc[mi][ni], a[mi], b[ni]);
            }
        }

        // ---- C store: d0,d1 -> (row g, col tg*2..+1); d2,d3 -> row g+8
        int g = lane >> 2, tg = lane & 3;
#pragma unroll
        for (int mi = 0; mi < MI; mi++) {
            int r0 = base + wm + mi * 16 + g;
#pragma unroll
            for (int ni = 0; ni < NI; ni++) {
                int col = noff + wn + ni * 8 + tg * 2;
                *(float2*)(C + (size_t)r0 * CS + col)       = make_float2(acc[mi][ni][0], acc[mi][ni][1]);
                *(float2*)(C + (size_t)(r0 + 8) * CS + col) = make_float2(acc[mi][ni][2], acc[mi][ni][3]);
            }
        }

        // ---- fused attention logits (h-columns: slab 0 only)
        int head = wid % WNN;
        if (slab == 0 && !(L == 1 && head != 0)) {
            float s_w[NI * 2], d_w[NI * 2];
#pragma unroll
            for (int ni = 0; ni < NI; ni++) {
                int ci = ni * 8 + tg * 2;
                s_w[ni * 2]     = __ldg(attS + head * 32 + ci);
                s_w[ni * 2 + 1] = __ldg(attS + head * 32 + ci + 1);
                d_w[ni * 2]     = __ldg(attD + head * 32 + ci);
                d_w[ni * 2 + 1] = __ldg(attD + head * 32 + ci + 1);
            }
#pragma unroll
            for (int mi = 0; mi < MI; mi++) {
                float s0 = 0.f, d0 = 0.f, s1 = 0.f, d1 = 0.f;
#pragma unroll
                for (int ni = 0; ni < NI; ni++) {
                    s0 = fmaf(acc[mi][ni][0], s_w[ni * 2], fmaf(acc[mi][ni][1], s_w[ni * 2 + 1], s0));
                    d0 = fmaf(acc[mi][ni][0], d_w[ni * 2], fmaf(acc[mi][ni][1], d_w[ni * 2 + 1], d0));
                    s1 = fmaf(acc[mi][ni][2], s_w[ni * 2], fmaf(acc[mi][ni][3], s_w[ni * 2 + 1], s1));
                    d1 = fmaf(acc[mi][ni][2], d_w[ni * 2], fmaf(acc[mi][ni][3], d_w[ni * 2 + 1], d1));
                }
#pragma unroll
                for (int o = 1; o <= 2; o <<= 1) {
                    s0 += __shfl_xor_sync(0xffffffffu, s0, o);
                    d0 += __shfl_xor_sync(0xffffffffu, d0, o);
                    s1 += __shfl_xor_sync(0xffffffffu, s1, o);
                    d1 += __shfl_xor_sync(0xffffffffu, d1, o);
                }
                if (tg == 0) {
                    int r0 = base + wm + mi * 16 + g;
                    int r1 = r0 + 8;
                    if (L == 0) {
                        if (r0 < M) { g_as0[r0 * 4 + head] = s0; g_ad0[r0 * 4 + head] = d0; }
                        if (r1 < M) { g_as0[r1 * 4 + head] = s1; g_ad0[r1 * 4 + head] = d1; }
                    } else {
                        if (r0 < M) { g_as1[r0] = s0; g_ad1[r0] = d0; }
                        if (r1 < M) { g_as1[r1] = s1; g_ad1[r1] = d1; }
                    }
                }
            }
        }
        if (slab + 1 < NSLAB) __syncthreads();   // protect B restage
    }
}

// ---------------- layer-0 aggregation: warp per dst node --------------------
// Single pass over edges: weights exp(leaky(e)) computed lane-parallel per
// 32-edge chunk into smem (with src indices), denominator accumulated; gather
// uses LDS broadcast. (No max subtraction: softmax shift-invariant, |e|<<88.)
__global__ void k_agg0(const float* __restrict__ bias0, const float* __restrict__ linb0, int n) {
    __shared__ float sw[8][32][4];
    __shared__ int   ss[8][32];
    int gw = (blockIdx.x * blockDim.x + threadIdx.x) >> 5;
    int warp = threadIdx.x >> 5;
    int lane = threadIdx.x & 31;
    if (gw >= n) return;
    int beg = g_rowptr[gw], end = g_rowptr[gw + 1];

    int   hsel = lane & 3;
    float4 ad4 = *(const float4*)(g_ad0 + gw * 4);
    float adh = (hsel == 0) ? ad4.x : (hsel == 1) ? ad4.y : (hsel == 2) ? ad4.z : ad4.w;

    float dn = 0.f;
    float acc0 = 0.f, acc1 = 0.f, acc2 = 0.f, acc3 = 0.f;

    for (int cbeg = beg; cbeg < end; cbeg += 32) {
        int cnt = min(32, end - cbeg);
#pragma unroll
        for (int c = 0; c < 4; c++) {
            int ei = c * 8 + (lane >> 2);
            float w = 0.f;
            if (ei < cnt) {
                int s = g_csr_src[cbeg + ei];
                if (hsel == 0) ss[warp][ei] = s;
                float ev = g_as0[s * 4 + hsel] + adh;
                ev = ev > 0.f ? ev : 0.2f * ev;
                w = __expf(ev);
            }
            sw[warp][ei][hsel] = w;
            dn += w;
        }
        __syncwarp();
#pragma unroll 2
        for (int e2 = 0; e2 < cnt; e2++) {
            float4 w4 = *(const float4*)&sw[warp][e2][0];
            int s = ss[warp][e2];
            const float* row = g_l0 + (size_t)s * 256;
            acc0 = fmaf(w4.x, row[lane],      acc0);
            acc1 = fmaf(w4.y, row[32 + lane], acc1);
            acc2 = fmaf(w4.z, row[64 + lane], acc2);
            acc3 = fmaf(w4.w, row[96 + lane], acc3);
        }
        __syncwarp();
    }

#pragma unroll
    for (int o = 4; o <= 16; o <<= 1) dn += __shfl_xor_sync(0xffffffffu, dn, o);
    float invh = 1.f / (dn + 1e-16f);
    float inv0 = __shfl_sync(0xffffffffu, invh, 0);
    float inv1 = __shfl_sync(0xffffffffu, invh, 1);
    float inv2 = __shfl_sync(0xffffffffu, invh, 2);
    float inv3 = __shfl_sync(0xffffffffu, invh, 3);

    const float* skip = g_l0 + (size_t)gw * 256 + 128;
    float o0 = acc0 * inv0 + bias0[lane]      + linb0[lane]      + skip[lane];
    float o1 = acc1 * inv1 + bias0[32 + lane] + linb0[32 + lane] + skip[32 + lane];
    float o2 = acc2 * inv2 + bias0[64 + lane] + linb0[64 + lane] + skip[64 + lane];
    float o3 = acc3 * inv3 + bias0[96 + lane] + linb0[96 + lane] + skip[96 + lane];
    o0 = o0 > 0.f ? o0 : (__expf(o0) - 1.f);
    o1 = o1 > 0.f ? o1 : (__expf(o1) - 1.f);
    o2 = o2 > 0.f ? o2 : (__expf(o2) - 1.f);
    o3 = o3 > 0.f ? o3 : (__expf(o3) - 1.f);

    size_t rb = (size_t)gw * 128;
    __nv_bfloat16 h;
    h = __float2bfloat16_rn(o0); g_hh[rb + lane]      = h; g_hl[rb + lane]      = __float2bfloat16_rn(o0 - __bfloat162float(h));
    h = __float2bfloat16_rn(o1); g_hh[rb + 32 + lane] = h; g_hl[rb + 32 + lane] = __float2bfloat16_rn(o1 - __bfloat162float(h));
    h = __float2bfloat16_rn(o2); g_hh[rb + 64 + lane] = h; g_hl[rb + 64 + lane] = __float2bfloat16_rn(o2 - __bfloat162float(h));
    h = __float2bfloat16_rn(o3); g_hh[rb + 96 + lane] = h; g_hl[rb + 96 + lane] = __float2bfloat16_rn(o3 - __bfloat162float(h));
}

// ---------------- layer-1 aggregation: warp per dst node --------------------
__global__ void k_agg1(const float* __restrict__ bias1, const float* __restrict__ linb1,
                       float* __restrict__ out, int n) {
    __shared__ float sw1[8][32];
    __shared__ int   ss1[8][32];
    int gw = (blockIdx.x * blockDim.x + threadIdx.x) >> 5;
    int warp = threadIdx.x >> 5;
    int lane = threadIdx.x & 31;
    if (gw >= n) return;
    int beg = g_rowptr[gw], end = g_rowptr[gw + 1];
    float ad = g_ad1[gw];

    float dn = 0.f;
    float acc = 0.f;
    for (int cbeg = beg; cbeg < end; cbeg += 32) {
        int cnt = min(32, end - cbeg);
        float w = 0.f;
        if (lane < cnt) {
            int s = g_csr_src[cbeg + lane];
            ss1[warp][lane] = s;
            float ev = g_as1[s] + ad;
            ev = ev > 0.f ? ev : 0.2f * ev;
            w = __expf(ev);
        }
        sw1[warp][lane] = w;
        dn += w;
        __syncwarp();
#pragma unroll 2
        for (int e2 = 0; e2 < cnt; e2++) {
            int s = ss1[warp][e2];
            acc = fmaf(sw1[warp][e2], g_l1[(size_t)s * 64 + lane], acc);
        }
        __syncwarp();
    }
#pragma unroll
    for (int o = 16; o; o >>= 1) dn += __shfl_xor_sync(0xffffffffu, dn, o);
    float inv = 1.f / (dn + 1e-16f);

    out[(size_t)gw * 32 + lane] =
        acc * inv + bias1[lane] + linb1[lane] + g_l1[(size_t)gw * 64 + 32 + lane];
}

// ---------------- launcher ---------------------------------------------------
extern "C" void kernel_launch(void* const* d_in, const int* in_sizes, int n_in,
                              void* d_out, int out_size) {
    const float* x   = (const float*)d_in[0];
    const int*   ei  = (const int*)  d_in[1];
    const float* W0  = (const float*)d_in[2];
    const float* as0 = (const float*)d_in[3];
    const float* ad0 = (const float*)d_in[4];
    const float* b0  = (const float*)d_in[5];
    const float* lW0 = (const float*)d_in[6];
    const float* lb0 = (const float*)d_in[7];
    const float* W1  = (const float*)d_in[8];
    const float* as1 = (const float*)d_in[9];
    const float* ad1 = (const float*)d_in[10];
    const float* b1  = (const float*)d_in[11];
    const float* lW1 = (const float*)d_in[12];
    const float* lb1 = (const float*)d_in[13];
    float* out = (float*)d_out;

    int n = in_sizes[0] / 128;
    int e = in_sizes[1] / 2;
    int etot = n + e;
    int nb = (n + SCAN_BS - 1) / SCAN_BS;
    int ntiles = (n + 127) / 128;

    const int smem0 = 2 * 128 * 272 + 2 * 128 * 272;  // 139264
    const int smem1 = 2 * 128 * 272 + 2 * 64 * 272;   // 104448
    static bool inited = false;
    static cudaStream_t s2;
    static cudaEvent_t evFork, evCsr;
    if (!inited) {
        cudaFuncSetAttribute(k_mma<0>, cudaFuncAttributeMaxDynamicSharedMemorySize, smem0);
        cudaFuncSetAttribute(k_mma<1>, cudaFuncAttributeMaxDynamicSharedMemorySize, smem1);
        cudaStreamCreateWithFlags(&s2, cudaStreamNonBlocking);
        cudaEventCreateWithFlags(&evFork, cudaEventDisableTiming);
        cudaEventCreateWithFlags(&evCsr, cudaEventDisableTiming);
        inited = true;
    }

    // fork: CSR chain on s2, concurrent with weight split + GEMM0
    cudaEventRecord(evFork, 0);
    cudaStreamWaitEvent(s2, evFork, 0);

    k_zero_deg<<<(n + 255) / 256, 256, 0, s2>>>(n);
    k_hist<<<(etot + 255) / 256, 256, 0, s2>>>(ei, e, etot);
    k_scan1<<<nb, SCAN_BS, 0, s2>>>(n);
    k_scan23<<<(n + 255) / 256, 256, 0, s2>>>(n);
    k_scatter<<<(etot + 255) / 256, 256, 0, s2>>>(ei, e, etot);
    cudaEventRecord(evCsr, s2);

    // default stream: weights + layer-0 GEMM (fused x split + logits)
    k_setupW<<<(128 * 128 + 255) / 256, 256>>>(W0, lW0, W1, lW1);
    k_mma<0><<<ntiles, 256, smem0>>>(x, as0, ad0, n);

    // join: aggregation needs CSR
    cudaStreamWaitEvent(0, evCsr, 0);
    k_agg0<<<(n + 7) / 8, 256>>>(b0, lb0, n);

    // layer 1
    k_mma<1><<<ntiles, 256, smem1>>>(x, as1, ad1, n);
    k_agg1<<<(n + 7) / 8, 256>>>(b1, lb1, out, n);
}